// round 8
// baseline (speedup 1.0000x reference)
#include <cuda_runtime.h>
#include <cuda_bf16.h>
#include <cstdint>

#define N_NODES 50000
#define E_MAX   600000
#define D_DIM   128
#define R_REL   4
#define L_LAY   3
#define KTOT    640          // 128 (root) + 4*128 (W)
#define NR4     (N_NODES * R_REL)

// ---------------------------------------------------------------------------
// Static device scratch (no runtime allocation allowed)
// ---------------------------------------------------------------------------
__device__ __nv_bfloat16 g_xhiA[(size_t)N_NODES * D_DIM];
__device__ __nv_bfloat16 g_xloA[(size_t)N_NODES * D_DIM];
__device__ __nv_bfloat16 g_xhiB[(size_t)N_NODES * D_DIM];
__device__ __nv_bfloat16 g_xloB[(size_t)N_NODES * D_DIM];
// Transposed + bf16-split stacked weights: Bt[l][n][k], k in [0,640)
__device__ __nv_bfloat16 g_Bhi[L_LAY][D_DIM][KTOT];
__device__ __nv_bfloat16 g_Blo[L_LAY][D_DIM][KTOT];
// Edge sort (key = dst*4 + relation)
__device__ int g_sorted[E_MAX];
__device__ int g_rowstart[NR4 + 1];
__device__ int g_cursor[NR4];
__device__ int g_bsum[256];

// ---------------------------------------------------------------------------
// Helpers
// ---------------------------------------------------------------------------
#define SWZ128(off) ((off) ^ (((off) >> 3) & 0x70))

__device__ __forceinline__ uint32_t smem_u32(const void* p) {
    uint32_t a;
    asm("{ .reg .u64 t; cvta.to.shared.u64 t, %1; cvt.u32.u64 %0, t; }"
        : "=r"(a) : "l"(p));
    return a;
}
__device__ __forceinline__ void cp16(uint32_t d, const void* s) {
    asm volatile("cp.async.cg.shared.global [%0], [%1], 16;" :: "r"(d), "l"(s));
}
__device__ __forceinline__ void cp16z(uint32_t d, const void* s, int bytes) {
    asm volatile("cp.async.cg.shared.global [%0], [%1], 16, %2;"
                 :: "r"(d), "l"(s), "r"(bytes));
}
#define CP_COMMIT() asm volatile("cp.async.commit_group;" ::: "memory")
#define CP_WAIT0()  asm volatile("cp.async.wait_group 0;" ::: "memory")

__device__ __forceinline__ void ldmatrix_x4(uint32_t& r0, uint32_t& r1,
                                            uint32_t& r2, uint32_t& r3,
                                            uint32_t addr) {
    asm volatile("ldmatrix.sync.aligned.m8n8.x4.shared.b16 {%0,%1,%2,%3}, [%4];"
                 : "=r"(r0), "=r"(r1), "=r"(r2), "=r"(r3) : "r"(addr));
}
__device__ __forceinline__ void mma_bf16(float* c, const uint32_t* a,
                                         uint32_t b0, uint32_t b1) {
    asm volatile(
        "mma.sync.aligned.m16n8k16.row.col.f32.bf16.bf16.f32 "
        "{%0,%1,%2,%3}, {%4,%5,%6,%7}, {%8,%9}, {%0,%1,%2,%3};"
        : "+f"(c[0]), "+f"(c[1]), "+f"(c[2]), "+f"(c[3])
        : "r"(a[0]), "r"(a[1]), "r"(a[2]), "r"(a[3]), "r"(b0), "r"(b1));
}

__device__ __forceinline__ float bf_lo(uint32_t u) {
    return __bfloat162float(__ushort_as_bfloat16((unsigned short)(u & 0xffff)));
}
__device__ __forceinline__ float bf_hi(uint32_t u) {
    return __bfloat162float(__ushort_as_bfloat16((unsigned short)(u >> 16)));
}
__device__ __forceinline__ uint32_t pack2bf(float a, float b) {
    return ((uint32_t)__bfloat16_as_ushort(__float2bfloat16(b)) << 16) |
           (uint32_t)__bfloat16_as_ushort(__float2bfloat16(a));
}
__device__ __forceinline__ void split1(float v, float& hi, float& lo) {
    __nv_bfloat16 h = __float2bfloat16(v);
    hi = __bfloat162float(h);
    lo = v - hi;
}

// ---------------------------------------------------------------------------
// Kernel: embed -> bf16 hi/lo split
// ---------------------------------------------------------------------------
__global__ void embed_kernel(const int* __restrict__ node_type,
                             const float* __restrict__ emb,
                             __nv_bfloat16* __restrict__ xhi,
                             __nv_bfloat16* __restrict__ xlo, int n)
{
    int idx = blockIdx.x * blockDim.x + threadIdx.x;
    if (idx >= n * 32) return;
    int node = idx >> 5;
    int q    = idx & 31;
    float4 v = reinterpret_cast<const float4*>(emb + (size_t)node_type[node] * D_DIM)[q];
    float h0, l0, h1, l1, h2, l2, h3, l3;
    split1(v.x, h0, l0); split1(v.y, h1, l1);
    split1(v.z, h2, l2); split1(v.w, h3, l3);
    *reinterpret_cast<uint2*>(xhi + (size_t)node * D_DIM + q * 4) =
        make_uint2(pack2bf(h0, h1), pack2bf(h2, h3));
    *reinterpret_cast<uint2*>(xlo + (size_t)node * D_DIM + q * 4) =
        make_uint2(pack2bf(l0, l1), pack2bf(l2, l3));
}

// ---------------------------------------------------------------------------
// Kernel: weight prep (transpose + split), once per launch
// ---------------------------------------------------------------------------
__global__ void prep_kernel(const float* __restrict__ W,
                            const float* __restrict__ root)
{
    int idx = blockIdx.x * blockDim.x + threadIdx.x;
    const int TOT = L_LAY * D_DIM * KTOT;
    if (idx >= TOT) return;
    int l  = idx / (D_DIM * KTOT);
    int r0 = idx % (D_DIM * KTOT);
    int nn = r0 / KTOT;
    int k  = r0 % KTOT;
    float v;
    if (k < D_DIM) {
        v = root[((size_t)l * D_DIM + k) * D_DIM + nn];
    } else {
        int kk = k - D_DIM;
        int r  = kk >> 7;
        int k2 = kk & 127;
        v = W[((((size_t)l * R_REL) + r) * D_DIM + k2) * D_DIM + nn];
    }
    float hi, lo;
    split1(v, hi, lo);
    g_Bhi[l][nn][k] = __float2bfloat16(hi);
    g_Blo[l][nn][k] = __float2bfloat16(lo);
}

// ---------------------------------------------------------------------------
// Counting sort of edges by key = dst*4 + rel  (3-phase parallel scan)
// ---------------------------------------------------------------------------
__global__ void hist_kernel(const int* __restrict__ edge_index,
                            const int* __restrict__ edge_type, int E)
{
    int idx = blockIdx.x * blockDim.x + threadIdx.x;
    if (idx >= E) return;
    atomicAdd(&g_cursor[edge_index[E + idx] * 4 + edge_type[idx]], 1);
}

__global__ __launch_bounds__(1024)
void scanA_kernel(int n4)
{
    __shared__ int warp_sums[32];
    const int tid  = threadIdx.x;
    const int lane = tid & 31;
    const int wrp  = tid >> 5;
    const int i    = blockIdx.x * 1024 + tid;
    int v = (i < n4) ? g_cursor[i] : 0;
    int x = v;
    #pragma unroll
    for (int d = 1; d < 32; d <<= 1) {
        int t = __shfl_up_sync(0xffffffffu, x, d);
        if (lane >= d) x += t;
    }
    if (lane == 31) warp_sums[wrp] = x;
    __syncthreads();
    if (wrp == 0) {
        int s = warp_sums[lane];
        #pragma unroll
        for (int d = 1; d < 32; d <<= 1) {
            int t = __shfl_up_sync(0xffffffffu, s, d);
            if (lane >= d) s += t;
        }
        warp_sums[lane] = s;
    }
    __syncthreads();
    int excl = x - v + (wrp ? warp_sums[wrp - 1] : 0);
    if (i < n4) g_rowstart[i] = excl;
    if (tid == 1023) g_bsum[blockIdx.x] = excl + v;
}

// Exclusive scan of <=256 block totals.
__global__ __launch_bounds__(256)
void scanB_kernel(int nb)
{
    __shared__ int ws[8];
    const int tid  = threadIdx.x;
    const int lane = tid & 31;
    const int wrp  = tid >> 5;
    int v = (tid < nb) ? g_bsum[tid] : 0;
    int x = v;
    #pragma unroll
    for (int d = 1; d < 32; d <<= 1) {
        int t = __shfl_up_sync(0xffffffffu, x, d);
        if (lane >= d) x += t;
    }
    if (lane == 31) ws[wrp] = x;
    __syncthreads();
    if (wrp == 0) {
        int s = (lane < 8) ? ws[lane] : 0;
        #pragma unroll
        for (int d = 1; d < 32; d <<= 1) {
            int t = __shfl_up_sync(0xffffffffu, s, d);
            if (lane >= d) s += t;
        }
        if (lane < 8) ws[lane] = s;
    }
    __syncthreads();
    int excl = x - v + (wrp ? ws[wrp - 1] : 0);
    if (tid < nb) g_bsum[tid] = excl;
}

__global__ __launch_bounds__(1024)
void scanC_kernel(int n4, int E)
{
    const int i = blockIdx.x * 1024 + threadIdx.x;
    if (i < n4) {
        int v = g_rowstart[i] + g_bsum[blockIdx.x];
        g_rowstart[i] = v;
        g_cursor[i]   = v;
    } else if (i == n4) {
        g_rowstart[n4] = E;
    }
}

__global__ void reorder_kernel(const int* __restrict__ edge_index,
                               const int* __restrict__ edge_type, int E)
{
    int idx = blockIdx.x * blockDim.x + threadIdx.x;
    if (idx >= E) return;
    int key = edge_index[E + idx] * 4 + edge_type[idx];
    int pos = atomicAdd(&g_cursor[key], 1);
    g_sorted[pos] = edge_index[idx];   // src only
}

// ---------------------------------------------------------------------------
// FUSED layer kernel: per 64-row tile,
//   y = lrelu( x@root + sum_r agg_r(x) @ W_r + bias )
// 256 threads = 8 warps (2 m-groups x 4 n-groups, warp tile 32x32).
// SMEM 96KB: A tile (64x128 bf16 hi/lo as 2 subtiles of [64][64], 128B rows,
// SWZ128) + B tile (128x128 bf16 hi/lo as 2 subtiles of [128][64]).
// Phases: root, r=0..3. W_(r) prefetched via cp.async overlapping agg(r).
// ---------------------------------------------------------------------------
#define FA_HI 0
#define FA_LO 16384
#define FB_HI 32768
#define FB_LO 65536
#define F_TOTAL 98304

__global__ __launch_bounds__(256, 2)
void fused_layer_kernel(const __nv_bfloat16* __restrict__ xhi,
                        const __nv_bfloat16* __restrict__ xlo,
                        const __nv_bfloat16* __restrict__ Bhi,   // [128][640]
                        const __nv_bfloat16* __restrict__ Blo,
                        const float* __restrict__ bias_l,
                        __nv_bfloat16* __restrict__ yhi,         // null on final
                        __nv_bfloat16* __restrict__ ylo,
                        float* __restrict__ yf32,                // null unless final
                        int n)
{
    extern __shared__ __align__(1024) char smem[];
    const uint32_t sb = smem_u32(smem);
    const int tid    = threadIdx.x;
    const int lane   = tid & 31;
    const int wid    = tid >> 5;
    const int warp_m = wid & 1;     // 0..1 -> 32 rows each
    const int warp_n = wid >> 1;    // 0..3 -> 32 cols each
    const int m0     = blockIdx.x * 64;

    float acc[2][4][4];
    #pragma unroll
    for (int i = 0; i < 2; i++)
        #pragma unroll
        for (int j = 0; j < 4; j++)
            #pragma unroll
            for (int q = 0; q < 4; q++) acc[i][j][q] = 0.f;

    // ---- B loader: W slice [128 n][128 k] hi/lo at k-offset kofs ----
    auto load_B = [&](int kofs) {
        #pragma unroll
        for (int it = 0; it < 8; it++) {
            int g   = it * 256 + tid;     // 0..2047 granules per array
            int s   = g >> 10;            // subtile
            int row = (g >> 3) & 127;
            int q   = g & 7;
            uint32_t off = (uint32_t)(s * 16384) + SWZ128((uint32_t)(row * 128 + q * 16));
            const __nv_bfloat16* ph = Bhi + (size_t)row * KTOT + kofs + s * 64 + q * 8;
            const __nv_bfloat16* pl = Blo + (size_t)row * KTOT + kofs + s * 64 + q * 8;
            cp16(sb + FB_HI + off, ph);
            cp16(sb + FB_LO + off, pl);
        }
    };

    // ---- A loader (root phase): x rows m0..m0+63, K=128 ----
    auto load_A_root = [&]() {
        #pragma unroll
        for (int it = 0; it < 4; it++) {
            int g   = it * 256 + tid;     // 0..1023 granules per array
            int s   = g >> 9;
            int row = (g >> 3) & 63;
            int q   = g & 7;
            uint32_t off = (uint32_t)(s * 8192) + SWZ128((uint32_t)(row * 128 + q * 16));
            int bytes = (m0 + row < n) ? 16 : 0;
            cp16z(sb + FA_HI + off, xhi + (size_t)(m0 + row) * D_DIM + s * 64 + q * 8, bytes);
            cp16z(sb + FA_LO + off, xlo + (size_t)(m0 + row) * D_DIM + s * 64 + q * 8, bytes);
        }
    };

    // ---- MMA: accumulate A[64x128] @ B[128x128]^T into acc ----
    auto do_mma = [&]() {
        #pragma unroll
        for (int ks = 0; ks < 8; ks++) {
            const int s  = ks >> 2;
            const int k0 = (ks & 3) * 16;
            uint32_t bh[2][4], bl[2][4];
            #pragma unroll
            for (int p = 0; p < 2; p++) {
                int nrow = warp_n * 32 + p * 16 + (lane & 7) + ((lane >> 4) << 3);
                uint32_t off = (uint32_t)(s * 16384) +
                    SWZ128((uint32_t)(nrow * 128 + k0 * 2 + ((lane & 8) ? 16 : 0)));
                ldmatrix_x4(bh[p][0], bh[p][1], bh[p][2], bh[p][3], sb + FB_HI + off);
                ldmatrix_x4(bl[p][0], bl[p][1], bl[p][2], bl[p][3], sb + FB_LO + off);
            }
            #pragma unroll
            for (int m = 0; m < 2; m++) {
                int arow = warp_m * 32 + m * 16 + (lane & 15);
                uint32_t off = (uint32_t)(s * 8192) +
                    SWZ128((uint32_t)(arow * 128 + k0 * 2 + ((lane >> 4) << 4)));
                uint32_t ah[4], al[4];
                ldmatrix_x4(ah[0], ah[1], ah[2], ah[3], sb + FA_HI + off);
                ldmatrix_x4(al[0], al[1], al[2], al[3], sb + FA_LO + off);
                #pragma unroll
                for (int p = 0; p < 2; p++) {
                    #pragma unroll
                    for (int t = 0; t < 2; t++) {
                        int nt = p * 2 + t;
                        mma_bf16(acc[m][nt], ah, bh[p][t * 2], bh[p][t * 2 + 1]);
                        mma_bf16(acc[m][nt], ah, bl[p][t * 2], bl[p][t * 2 + 1]);
                        mma_bf16(acc[m][nt], al, bh[p][t * 2], bh[p][t * 2 + 1]);
                    }
                }
            }
        }
    };

    // ---- aggregation of relation r into A tile (register acc, smem store) ----
    auto agg = [&](int r) {
        #pragma unroll 1
        for (int i = 0; i < 8; i++) {
            int row = wid * 8 + i;
            int d   = m0 + row;
            float a0 = 0.f, a1 = 0.f, a2 = 0.f, a3 = 0.f;
            if (d < n) {
                int e0 = g_rowstart[d * 4 + r];
                int e1 = g_rowstart[d * 4 + r + 1];
                for (int e = e0; e < e1; e++) {
                    int src = __ldg(&g_sorted[e]);
                    uint2 vh = *reinterpret_cast<const uint2*>(
                        xhi + (size_t)src * D_DIM + lane * 4);
                    uint2 vl = *reinterpret_cast<const uint2*>(
                        xlo + (size_t)src * D_DIM + lane * 4);
                    a0 += bf_lo(vh.x) + bf_lo(vl.x);
                    a1 += bf_hi(vh.x) + bf_hi(vl.x);
                    a2 += bf_lo(vh.y) + bf_lo(vl.y);
                    a3 += bf_hi(vh.y) + bf_hi(vl.y);
                }
            }
            float h0, l0, h1, l1, h2, l2, h3, l3;
            split1(a0, h0, l0); split1(a1, h1, l1);
            split1(a2, h2, l2); split1(a3, h3, l3);
            int s = lane >> 4;
            uint32_t off = (uint32_t)(s * 8192) +
                SWZ128((uint32_t)(row * 128 + (lane & 15) * 8));
            *reinterpret_cast<uint2*>(smem + FA_HI + off) =
                make_uint2(pack2bf(h0, h1), pack2bf(h2, h3));
            *reinterpret_cast<uint2*>(smem + FA_LO + off) =
                make_uint2(pack2bf(l0, l1), pack2bf(l2, l3));
        }
    };

    // ---- prologue: root B + root A ----
    load_B(0);
    load_A_root();
    CP_COMMIT();
    CP_WAIT0();
    __syncthreads();

    // ---- 5 phases: root, r=0..3 ----
    #pragma unroll 1
    for (int p = 0; p < 5; p++) {
        do_mma();
        __syncthreads();                 // everyone done reading A & B
        if (p < 4) {
            load_B(128 + p * 128);       // W_(r=p), overlaps agg below
            CP_COMMIT();
            agg(p);                      // writes A tile (STS)
            CP_WAIT0();
            __syncthreads();             // A stores + B async visible
        }
    }

    // ---- epilogue: bias + leaky_relu ----
    #pragma unroll
    for (int nt = 0; nt < 4; nt++) {
        int col = warp_n * 32 + nt * 8 + (lane & 3) * 2;
        float2 b = *reinterpret_cast<const float2*>(bias_l + col);
        #pragma unroll
        for (int m = 0; m < 2; m++) {
            int row0 = m0 + warp_m * 32 + m * 16 + (lane >> 2);
            #pragma unroll
            for (int half = 0; half < 2; half++) {
                int row = row0 + half * 8;
                if (row < n) {
                    float v0 = acc[m][nt][half * 2 + 0] + b.x;
                    float v1 = acc[m][nt][half * 2 + 1] + b.y;
                    v0 = v0 > 0.f ? v0 : 0.01f * v0;
                    v1 = v1 > 0.f ? v1 : 0.01f * v1;
                    if (yf32) {
                        *reinterpret_cast<float2*>(yf32 + (size_t)row * D_DIM + col) =
                            make_float2(v0, v1);
                    } else {
                        float h0, l0, h1, l1;
                        split1(v0, h0, l0);
                        split1(v1, h1, l1);
                        *reinterpret_cast<uint32_t*>(yhi + (size_t)row * D_DIM + col) =
                            pack2bf(h0, h1);
                        *reinterpret_cast<uint32_t*>(ylo + (size_t)row * D_DIM + col) =
                            pack2bf(l0, l1);
                    }
                }
            }
        }
    }
}

// ---------------------------------------------------------------------------
// Launch
// ---------------------------------------------------------------------------
extern "C" void kernel_launch(void* const* d_in, const int* in_sizes, int n_in,
                              void* d_out, int out_size)
{
    const int*   node_type  = (const int*)  d_in[0];
    const int*   edge_index = (const int*)  d_in[1];
    const int*   edge_type  = (const int*)  d_in[2];
    const float* emb        = (const float*)d_in[3];
    const float* W          = (const float*)d_in[4];   // [L,R,D,D]
    const float* root       = (const float*)d_in[5];   // [L,D,D]
    const float* bias       = (const float*)d_in[6];   // [L,D]
    float*       out        = (float*)d_out;

    const int n  = in_sizes[0];
    const int E  = in_sizes[2];
    const int n4 = n * R_REL;

    __nv_bfloat16 *xhiA, *xloA, *xhiB, *xloB, *bhi, *blo;
    int* cursor;
    cudaGetSymbolAddress((void**)&xhiA, g_xhiA);
    cudaGetSymbolAddress((void**)&xloA, g_xloA);
    cudaGetSymbolAddress((void**)&xhiB, g_xhiB);
    cudaGetSymbolAddress((void**)&xloB, g_xloB);
    cudaGetSymbolAddress((void**)&bhi,  g_Bhi);
    cudaGetSymbolAddress((void**)&blo,  g_Blo);
    cudaGetSymbolAddress((void**)&cursor, g_cursor);

    cudaFuncSetAttribute(fused_layer_kernel,
                         cudaFuncAttributeMaxDynamicSharedMemorySize, F_TOTAL);

    // --- one-time per launch: embed split, weight prep, edge sort ---
    cudaMemsetAsync(cursor, 0, (size_t)n4 * sizeof(int));
    embed_kernel<<<(n * 32 + 255) / 256, 256>>>(node_type, emb, xhiA, xloA, n);
    {
        const int TOT = L_LAY * D_DIM * KTOT;
        prep_kernel<<<(TOT + 255) / 256, 256>>>(W, root);
    }
    hist_kernel<<<(E + 255) / 256, 256>>>(edge_index, edge_type, E);
    {
        const int nb = (n4 + 1023) / 1024;
        scanA_kernel<<<nb, 1024>>>(n4);
        scanB_kernel<<<1, 256>>>(nb);
        scanC_kernel<<<(n4 + 1 + 1023) / 1024, 1024>>>(n4, E);
    }
    reorder_kernel<<<(E + 255) / 256, 256>>>(edge_index, edge_type, E);

    const int fused_blocks = (n + 63) / 64;

    for (int l = 0; l < L_LAY; l++) {
        const __nv_bfloat16* xih = (l == 1) ? xhiB : xhiA;
        const __nv_bfloat16* xil = (l == 1) ? xloB : xloA;
        __nv_bfloat16* xoh = (l == 0) ? xhiB : xhiA;
        __nv_bfloat16* xol = (l == 0) ? xloB : xloA;

        if (l < L_LAY - 1) {
            fused_layer_kernel<<<fused_blocks, 256, F_TOTAL>>>(
                xih, xil,
                bhi + (size_t)l * D_DIM * KTOT,
                blo + (size_t)l * D_DIM * KTOT,
                bias + (size_t)l * D_DIM,
                xoh, xol, (float*)nullptr, n);
        } else {
            fused_layer_kernel<<<fused_blocks, 256, F_TOTAL>>>(
                xih, xil,
                bhi + (size_t)l * D_DIM * KTOT,
                blo + (size_t)l * D_DIM * KTOT,
                bias + (size_t)l * D_DIM,
                (__nv_bfloat16*)nullptr, (__nv_bfloat16*)nullptr, out, n);
        }
    }
}

// round 9
// speedup vs baseline: 1.5925x; 1.5925x over previous
#include <cuda_runtime.h>
#include <cuda_fp16.h>
#include <cstdint>

#define N_NODES 50000
#define E_MAX   600000
#define D_DIM   128
#define R_REL   4
#define L_LAY   3
#define KTOT    640           // 128 (root) + 4*128 (W)
#define KC      32            // K per pipeline stage
#define NCHUNK  (KTOT / KC)   // 20
#define NR4     (N_NODES * R_REL)

// ---------------------------------------------------------------------------
// Static device scratch (no runtime allocation allowed)
// ---------------------------------------------------------------------------
__device__ __half g_xA[(size_t)N_NODES * D_DIM];
__device__ __half g_xB[(size_t)N_NODES * D_DIM];
__device__ __half g_h [(size_t)N_NODES * R_REL * D_DIM];
// Transposed + fp16-split stacked weights: Bt[l][n][k], k in [0,640)
__device__ __half g_Whi[L_LAY][D_DIM][KTOT];
__device__ __half g_Wlo[L_LAY][D_DIM][KTOT];
// Edge sort (key = dst*4 + relation)
__device__ int g_sorted[E_MAX];
__device__ int g_rowstart[NR4 + 1];
__device__ int g_cursor[NR4];
__device__ int g_bsum[256];

// ---------------------------------------------------------------------------
// Helpers
// ---------------------------------------------------------------------------
#define SWZ64(off) ((off) ^ (((off) >> 3) & 0x30))

__device__ __forceinline__ uint32_t smem_u32(const void* p) {
    uint32_t a;
    asm("{ .reg .u64 t; cvta.to.shared.u64 t, %1; cvt.u32.u64 %0, t; }"
        : "=r"(a) : "l"(p));
    return a;
}
__device__ __forceinline__ void cp16(uint32_t d, const void* s) {
    asm volatile("cp.async.cg.shared.global [%0], [%1], 16;" :: "r"(d), "l"(s));
}
__device__ __forceinline__ void cp16z(uint32_t d, const void* s, int bytes) {
    asm volatile("cp.async.cg.shared.global [%0], [%1], 16, %2;"
                 :: "r"(d), "l"(s), "r"(bytes));
}
#define CP_COMMIT() asm volatile("cp.async.commit_group;" ::: "memory")
#define CP_WAIT(N)  asm volatile("cp.async.wait_group %0;" :: "n"(N) : "memory")

__device__ __forceinline__ void ldmatrix_x4(uint32_t& r0, uint32_t& r1,
                                            uint32_t& r2, uint32_t& r3,
                                            uint32_t addr) {
    asm volatile("ldmatrix.sync.aligned.m8n8.x4.shared.b16 {%0,%1,%2,%3}, [%4];"
                 : "=r"(r0), "=r"(r1), "=r"(r2), "=r"(r3) : "r"(addr));
}
__device__ __forceinline__ void mma_f16(float* c, const uint32_t* a,
                                        uint32_t b0, uint32_t b1) {
    asm volatile(
        "mma.sync.aligned.m16n8k16.row.col.f32.f16.f16.f32 "
        "{%0,%1,%2,%3}, {%4,%5,%6,%7}, {%8,%9}, {%0,%1,%2,%3};"
        : "+f"(c[0]), "+f"(c[1]), "+f"(c[2]), "+f"(c[3])
        : "r"(a[0]), "r"(a[1]), "r"(a[2]), "r"(a[3]), "r"(b0), "r"(b1));
}

__device__ __forceinline__ uint32_t pack2h(float a, float b) {
    __half2 h = __floats2half2_rn(a, b);
    return *reinterpret_cast<uint32_t*>(&h);
}

// ---------------------------------------------------------------------------
// Kernel: embed -> fp16
// ---------------------------------------------------------------------------
__global__ void embed_kernel(const int* __restrict__ node_type,
                             const float* __restrict__ emb,
                             __half* __restrict__ x, int n)
{
    int idx = blockIdx.x * blockDim.x + threadIdx.x;
    if (idx >= n * 32) return;
    int node = idx >> 5;
    int q    = idx & 31;
    float4 v = reinterpret_cast<const float4*>(emb + (size_t)node_type[node] * D_DIM)[q];
    *reinterpret_cast<uint2*>(x + (size_t)node * D_DIM + q * 4) =
        make_uint2(pack2h(v.x, v.y), pack2h(v.z, v.w));
}

// ---------------------------------------------------------------------------
// Kernel: weight prep (transpose + fp16 hi/lo split), once per launch
// ---------------------------------------------------------------------------
__global__ void prep_kernel(const float* __restrict__ W,
                            const float* __restrict__ root)
{
    int idx = blockIdx.x * blockDim.x + threadIdx.x;
    const int TOT = L_LAY * D_DIM * KTOT;
    if (idx >= TOT) return;
    int l  = idx / (D_DIM * KTOT);
    int r0 = idx % (D_DIM * KTOT);
    int nn = r0 / KTOT;
    int k  = r0 % KTOT;
    float v;
    if (k < D_DIM) {
        v = root[((size_t)l * D_DIM + k) * D_DIM + nn];
    } else {
        int kk = k - D_DIM;
        int r  = kk >> 7;
        int k2 = kk & 127;
        v = W[((((size_t)l * R_REL) + r) * D_DIM + k2) * D_DIM + nn];
    }
    __half hi = __float2half_rn(v);
    __half lo = __float2half_rn(v - __half2float(hi));
    g_Whi[l][nn][k] = hi;
    g_Wlo[l][nn][k] = lo;
}

// ---------------------------------------------------------------------------
// Counting sort of edges by key = dst*4 + rel  (3-phase parallel scan)
// ---------------------------------------------------------------------------
__global__ void hist_kernel(const int* __restrict__ edge_index,
                            const int* __restrict__ edge_type, int E)
{
    int idx = blockIdx.x * blockDim.x + threadIdx.x;
    if (idx >= E) return;
    atomicAdd(&g_cursor[edge_index[E + idx] * 4 + edge_type[idx]], 1);
}

__global__ __launch_bounds__(1024)
void scanA_kernel(int n4)
{
    __shared__ int warp_sums[32];
    const int tid  = threadIdx.x;
    const int lane = tid & 31;
    const int wrp  = tid >> 5;
    const int i    = blockIdx.x * 1024 + tid;
    int v = (i < n4) ? g_cursor[i] : 0;
    int x = v;
    #pragma unroll
    for (int d = 1; d < 32; d <<= 1) {
        int t = __shfl_up_sync(0xffffffffu, x, d);
        if (lane >= d) x += t;
    }
    if (lane == 31) warp_sums[wrp] = x;
    __syncthreads();
    if (wrp == 0) {
        int s = warp_sums[lane];
        #pragma unroll
        for (int d = 1; d < 32; d <<= 1) {
            int t = __shfl_up_sync(0xffffffffu, s, d);
            if (lane >= d) s += t;
        }
        warp_sums[lane] = s;
    }
    __syncthreads();
    int excl = x - v + (wrp ? warp_sums[wrp - 1] : 0);
    if (i < n4) g_rowstart[i] = excl;
    if (tid == 1023) g_bsum[blockIdx.x] = excl + v;
}

__global__ __launch_bounds__(256)
void scanB_kernel(int nb)
{
    __shared__ int ws[8];
    const int tid  = threadIdx.x;
    const int lane = tid & 31;
    const int wrp  = tid >> 5;
    int v = (tid < nb) ? g_bsum[tid] : 0;
    int x = v;
    #pragma unroll
    for (int d = 1; d < 32; d <<= 1) {
        int t = __shfl_up_sync(0xffffffffu, x, d);
        if (lane >= d) x += t;
    }
    if (lane == 31) ws[wrp] = x;
    __syncthreads();
    if (wrp == 0) {
        int s = (lane < 8) ? ws[lane] : 0;
        #pragma unroll
        for (int d = 1; d < 32; d <<= 1) {
            int t = __shfl_up_sync(0xffffffffu, s, d);
            if (lane >= d) s += t;
        }
        if (lane < 8) ws[lane] = s;
    }
    __syncthreads();
    int excl = x - v + (wrp ? ws[wrp - 1] : 0);
    if (tid < nb) g_bsum[tid] = excl;
}

__global__ __launch_bounds__(1024)
void scanC_kernel(int n4, int E)
{
    const int i = blockIdx.x * 1024 + threadIdx.x;
    if (i < n4) {
        int v = g_rowstart[i] + g_bsum[blockIdx.x];
        g_rowstart[i] = v;
        g_cursor[i]   = v;
    } else if (i == n4) {
        g_rowstart[n4] = E;
    }
}

__global__ void reorder_kernel(const int* __restrict__ edge_index,
                               const int* __restrict__ edge_type, int E)
{
    int idx = blockIdx.x * blockDim.x + threadIdx.x;
    if (idx >= E) return;
    int key = edge_index[E + idx] * 4 + edge_type[idx];
    int pos = atomicAdd(&g_cursor[key], 1);
    g_sorted[pos] = edge_index[idx];   // src only
}

// ---------------------------------------------------------------------------
// Kernel: CSR aggregation. One warp per dst node; fp16 in, fp32 acc, fp16 out.
//   h[dst, r*128+col] = sum over edges (src,r) of x[src, col]
// ---------------------------------------------------------------------------
__global__ __launch_bounds__(256)
void agg_kernel(const __half* __restrict__ x,
                __half* __restrict__ h, int n)
{
    int w = (blockIdx.x * blockDim.x + threadIdx.x) >> 5;
    int lane = threadIdx.x & 31;
    if (w >= n) return;

    float acc[R_REL][4];
    #pragma unroll
    for (int r = 0; r < R_REL; r++)
        #pragma unroll
        for (int j = 0; j < 4; j++) acc[r][j] = 0.f;

    int e0 = g_rowstart[w * 4];
    int e1 = g_rowstart[w * 4 + 4];
    int k0 = g_rowstart[w * 4 + 1];
    int k1 = g_rowstart[w * 4 + 2];
    int k2 = g_rowstart[w * 4 + 3];

    #pragma unroll 2
    for (int e = e0; e < e1; e++) {
        int src = __ldg(&g_sorted[e]);
        int r   = (e >= k2) ? 3 : (e >= k1) ? 2 : (e >= k0) ? 1 : 0;
        uint2 v = *reinterpret_cast<const uint2*>(x + (size_t)src * D_DIM + lane * 4);
        float2 f0 = __half22float2(*reinterpret_cast<__half2*>(&v.x));
        float2 f1 = __half22float2(*reinterpret_cast<__half2*>(&v.y));
        acc[r][0] += f0.x;
        acc[r][1] += f0.y;
        acc[r][2] += f1.x;
        acc[r][3] += f1.y;
    }

    #pragma unroll
    for (int r = 0; r < R_REL; r++) {
        size_t o = (size_t)w * (R_REL * D_DIM) + r * D_DIM + lane * 4;
        *reinterpret_cast<uint2*>(h + o) =
            make_uint2(pack2h(acc[r][0], acc[r][1]), pack2h(acc[r][2], acc[r][3]));
    }
}

// ---------------------------------------------------------------------------
// GEMM: y[m,0:128] = lrelu( [x|h][m,0:640] @ Wt^T + bias )
// A fp16 single stream; W fp16 hi+lo (2-term). CTA 128x128, 256 thr.
// cp.async double-buffered KC=32 stages; SW64 swizzle over 64B rows.
// ---------------------------------------------------------------------------
#define ST_A   0
#define ST_BHI 8192
#define ST_BLO 16384
#define ST_SIZE 24576
#define SM_TOTAL (2 * ST_SIZE)

__global__ __launch_bounds__(256, 2)
void gemm_mma_kernel(const __half* __restrict__ x,
                     const __half* __restrict__ h,
                     const __half* __restrict__ Whi,   // [128][640]
                     const __half* __restrict__ Wlo,
                     const float* __restrict__ bias_l,
                     __half* __restrict__ yh,          // null on final
                     float* __restrict__ yf32,         // null unless final
                     int n)
{
    extern __shared__ __align__(1024) char smem[];
    const uint32_t sb = smem_u32(smem);
    const int tid    = threadIdx.x;
    const int lane   = tid & 31;
    const int wid    = tid >> 5;
    const int warp_m = wid >> 2;        // 0..1 -> 64 rows
    const int warp_n = wid & 3;         // 0..3 -> 32 cols
    const int m0     = blockIdx.x * 128;

    float acc[4][4][4];
    #pragma unroll
    for (int i = 0; i < 4; i++)
        #pragma unroll
        for (int j = 0; j < 4; j++)
            #pragma unroll
            for (int q = 0; q < 4; q++) acc[i][j][q] = 0.f;

    auto load_stage = [&](int stage, int c) {
        const __half* A;
        int lda;
        if (c < 4) { A = x + c * KC; lda = D_DIM; }
        else       { A = h + (c - 4) * KC; lda = R_REL * D_DIM; }
        const uint32_t base = sb + stage * ST_SIZE;
        #pragma unroll
        for (int it = 0; it < 2; it++) {
            int f   = it * 256 + tid;     // 0..511
            int row = f >> 2;
            int q   = f & 3;
            uint32_t off = SWZ64((uint32_t)(row * 64 + q * 16));
            int bytes = (m0 + row < n) ? 16 : 0;
            cp16z(base + ST_A + off, A + (size_t)(m0 + row) * lda + q * 8, bytes);
        }
        #pragma unroll
        for (int it = 0; it < 2; it++) {
            int f   = it * 256 + tid;
            int row = f >> 2;             // n index 0..127
            int q   = f & 3;
            uint32_t off = SWZ64((uint32_t)(row * 64 + q * 16));
            cp16(base + ST_BHI + off, Whi + (size_t)row * KTOT + c * KC + q * 8);
            cp16(base + ST_BLO + off, Wlo + (size_t)row * KTOT + c * KC + q * 8);
        }
    };

    load_stage(0, 0);
    CP_COMMIT();

    for (int c = 0; c < NCHUNK; c++) {
        if (c + 1 < NCHUNK) {
            load_stage((c + 1) & 1, c + 1);
            CP_COMMIT();
            CP_WAIT(1);
        } else {
            CP_WAIT(0);
        }
        __syncthreads();

        const uint32_t base = sb + (c & 1) * ST_SIZE;
        #pragma unroll
        for (int ks = 0; ks < 2; ks++) {
            const int k0 = ks * 16;
            uint32_t bh[2][4], bl[2][4];
            #pragma unroll
            for (int p = 0; p < 2; p++) {
                int nb   = warp_n * 32 + p * 16;
                int row  = nb + (lane & 7) + ((lane >> 4) << 3);
                uint32_t off = SWZ64((uint32_t)(row * 64 + k0 * 2 + ((lane & 8) ? 16 : 0)));
                ldmatrix_x4(bh[p][0], bh[p][1], bh[p][2], bh[p][3], base + ST_BHI + off);
                ldmatrix_x4(bl[p][0], bl[p][1], bl[p][2], bl[p][3], base + ST_BLO + off);
            }
            #pragma unroll
            for (int m = 0; m < 4; m++) {
                int row  = warp_m * 64 + m * 16 + (lane & 15);
                uint32_t off = SWZ64((uint32_t)(row * 64 + k0 * 2 + ((lane >> 4) << 4)));
                uint32_t a[4];
                ldmatrix_x4(a[0], a[1], a[2], a[3], base + ST_A + off);
                #pragma unroll
                for (int p = 0; p < 2; p++) {
                    #pragma unroll
                    for (int t = 0; t < 2; t++) {
                        int nt = p * 2 + t;
                        mma_f16(acc[m][nt], a, bh[p][t * 2], bh[p][t * 2 + 1]);
                        mma_f16(acc[m][nt], a, bl[p][t * 2], bl[p][t * 2 + 1]);
                    }
                }
            }
        }
        __syncthreads();
    }

    // ---- epilogue: bias + leaky_relu ----
    #pragma unroll
    for (int nt = 0; nt < 4; nt++) {
        int col = warp_n * 32 + nt * 8 + (lane & 3) * 2;
        float2 b = *reinterpret_cast<const float2*>(bias_l + col);
        #pragma unroll
        for (int m = 0; m < 4; m++) {
            int row0 = m0 + warp_m * 64 + m * 16 + (lane >> 2);
            #pragma unroll
            for (int half = 0; half < 2; half++) {
                int row = row0 + half * 8;
                if (row < n) {
                    float v0 = acc[m][nt][half * 2 + 0] + b.x;
                    float v1 = acc[m][nt][half * 2 + 1] + b.y;
                    v0 = v0 > 0.f ? v0 : 0.01f * v0;
                    v1 = v1 > 0.f ? v1 : 0.01f * v1;
                    if (yf32) {
                        *reinterpret_cast<float2*>(yf32 + (size_t)row * D_DIM + col) =
                            make_float2(v0, v1);
                    } else {
                        *reinterpret_cast<uint32_t*>(yh + (size_t)row * D_DIM + col) =
                            pack2h(v0, v1);
                    }
                }
            }
        }
    }
}

// ---------------------------------------------------------------------------
// Launch
// ---------------------------------------------------------------------------
extern "C" void kernel_launch(void* const* d_in, const int* in_sizes, int n_in,
                              void* d_out, int out_size)
{
    const int*   node_type  = (const int*)  d_in[0];
    const int*   edge_index = (const int*)  d_in[1];
    const int*   edge_type  = (const int*)  d_in[2];
    const float* emb        = (const float*)d_in[3];
    const float* W          = (const float*)d_in[4];   // [L,R,D,D]
    const float* root       = (const float*)d_in[5];   // [L,D,D]
    const float* bias       = (const float*)d_in[6];   // [L,D]
    float*       out        = (float*)d_out;

    const int n  = in_sizes[0];
    const int E  = in_sizes[2];
    const int n4 = n * R_REL;

    __half *xA, *xB, *h, *whi, *wlo;
    int* cursor;
    cudaGetSymbolAddress((void**)&xA,  g_xA);
    cudaGetSymbolAddress((void**)&xB,  g_xB);
    cudaGetSymbolAddress((void**)&h,   g_h);
    cudaGetSymbolAddress((void**)&whi, g_Whi);
    cudaGetSymbolAddress((void**)&wlo, g_Wlo);
    cudaGetSymbolAddress((void**)&cursor, g_cursor);

    cudaFuncSetAttribute(gemm_mma_kernel,
                         cudaFuncAttributeMaxDynamicSharedMemorySize, SM_TOTAL);

    // --- one-time per launch: embed, weight prep, edge sort ---
    cudaMemsetAsync(cursor, 0, (size_t)n4 * sizeof(int));
    embed_kernel<<<(n * 32 + 255) / 256, 256>>>(node_type, emb, xA, n);
    {
        const int TOT = L_LAY * D_DIM * KTOT;
        prep_kernel<<<(TOT + 255) / 256, 256>>>(W, root);
    }
    hist_kernel<<<(E + 255) / 256, 256>>>(edge_index, edge_type, E);
    {
        const int nb = (n4 + 1023) / 1024;
        scanA_kernel<<<nb, 1024>>>(n4);
        scanB_kernel<<<1, 256>>>(nb);
        scanC_kernel<<<(n4 + 1 + 1023) / 1024, 1024>>>(n4, E);
    }
    reorder_kernel<<<(E + 255) / 256, 256>>>(edge_index, edge_type, E);

    const int agg_blocks  = (n * 32 + 255) / 256;
    const int gemm_blocks = (n + 127) / 128;

    for (int l = 0; l < L_LAY; l++) {
        const __half* xin = (l == 1) ? xB : xA;
        __half*       xout = (l == 0) ? xB : xA;

        agg_kernel<<<agg_blocks, 256>>>(xin, h, n);

        if (l < L_LAY - 1) {
            gemm_mma_kernel<<<gemm_blocks, 256, SM_TOTAL>>>(
                xin, h,
                whi + (size_t)l * D_DIM * KTOT,
                wlo + (size_t)l * D_DIM * KTOT,
                bias + (size_t)l * D_DIM,
                xout, (float*)nullptr, n);
        } else {
            gemm_mma_kernel<<<gemm_blocks, 256, SM_TOTAL>>>(
                xin, h,
                whi + (size_t)l * D_DIM * KTOT,
                wlo + (size_t)l * D_DIM * KTOT,
                bias + (size_t)l * D_DIM,
                (__half*)nullptr, out, n);
        }
    }
}

// round 10
// speedup vs baseline: 1.5977x; 1.0033x over previous
#include <cuda_runtime.h>
#include <cuda_fp16.h>
#include <cstdint>

#define N_NODES 50000
#define E_MAX   600000
#define D_DIM   128
#define R_REL   4
#define L_LAY   3
#define KTOT    640           // 128 (root) + 4*128 (W)
#define KC      32            // K per pipeline stage
#define NCHUNK  (KTOT / KC)   // 20
#define NR4     (N_NODES * R_REL)

// ---------------------------------------------------------------------------
// Static device scratch (no runtime allocation allowed)
// ---------------------------------------------------------------------------
__device__ __half g_xA[(size_t)N_NODES * D_DIM];
__device__ __half g_xB[(size_t)N_NODES * D_DIM];
__device__ __half g_h [(size_t)N_NODES * R_REL * D_DIM];
// Transposed + fp16-split stacked weights: Bt[l][n][k], k in [0,640)
__device__ __half g_Whi[L_LAY][D_DIM][KTOT];
__device__ __half g_Wlo[L_LAY][D_DIM][KTOT];
// Edge sort (key = dst*4 + relation)
__device__ int g_sorted[E_MAX];
__device__ int g_rowstart[NR4 + 1];
__device__ int g_cursor[NR4];
__device__ int g_bsum[256];

// ---------------------------------------------------------------------------
// Helpers
// ---------------------------------------------------------------------------
#define SWZ64(off) ((off) ^ (((off) >> 3) & 0x30))

__device__ __forceinline__ uint32_t smem_u32(const void* p) {
    uint32_t a;
    asm("{ .reg .u64 t; cvta.to.shared.u64 t, %1; cvt.u32.u64 %0, t; }"
        : "=r"(a) : "l"(p));
    return a;
}
__device__ __forceinline__ void cp16(uint32_t d, const void* s) {
    asm volatile("cp.async.cg.shared.global [%0], [%1], 16;" :: "r"(d), "l"(s));
}
__device__ __forceinline__ void cp16z(uint32_t d, const void* s, int bytes) {
    asm volatile("cp.async.cg.shared.global [%0], [%1], 16, %2;"
                 :: "r"(d), "l"(s), "r"(bytes));
}
#define CP_COMMIT() asm volatile("cp.async.commit_group;" ::: "memory")
#define CP_WAIT(N)  asm volatile("cp.async.wait_group %0;" :: "n"(N) : "memory")

__device__ __forceinline__ void ldmatrix_x4(uint32_t& r0, uint32_t& r1,
                                            uint32_t& r2, uint32_t& r3,
                                            uint32_t addr) {
    asm volatile("ldmatrix.sync.aligned.m8n8.x4.shared.b16 {%0,%1,%2,%3}, [%4];"
                 : "=r"(r0), "=r"(r1), "=r"(r2), "=r"(r3) : "r"(addr));
}
__device__ __forceinline__ void mma_f16(float* c, const uint32_t* a,
                                        uint32_t b0, uint32_t b1) {
    asm volatile(
        "mma.sync.aligned.m16n8k16.row.col.f32.f16.f16.f32 "
        "{%0,%1,%2,%3}, {%4,%5,%6,%7}, {%8,%9}, {%0,%1,%2,%3};"
        : "+f"(c[0]), "+f"(c[1]), "+f"(c[2]), "+f"(c[3])
        : "r"(a[0]), "r"(a[1]), "r"(a[2]), "r"(a[3]), "r"(b0), "r"(b1));
}

__device__ __forceinline__ uint32_t pack2h(float a, float b) {
    __half2 h = __floats2half2_rn(a, b);
    return *reinterpret_cast<uint32_t*>(&h);
}

// ---------------------------------------------------------------------------
// Kernel: embed -> fp16
// ---------------------------------------------------------------------------
__global__ void embed_kernel(const int* __restrict__ node_type,
                             const float* __restrict__ emb,
                             __half* __restrict__ x, int n)
{
    int idx = blockIdx.x * blockDim.x + threadIdx.x;
    if (idx >= n * 32) return;
    int node = idx >> 5;
    int q    = idx & 31;
    float4 v = reinterpret_cast<const float4*>(emb + (size_t)node_type[node] * D_DIM)[q];
    *reinterpret_cast<uint2*>(x + (size_t)node * D_DIM + q * 4) =
        make_uint2(pack2h(v.x, v.y), pack2h(v.z, v.w));
}

// ---------------------------------------------------------------------------
// Kernel: weight prep (transpose + fp16 hi/lo split), once per launch
// ---------------------------------------------------------------------------
__global__ void prep_kernel(const float* __restrict__ W,
                            const float* __restrict__ root)
{
    int idx = blockIdx.x * blockDim.x + threadIdx.x;
    const int TOT = L_LAY * D_DIM * KTOT;
    if (idx >= TOT) return;
    int l  = idx / (D_DIM * KTOT);
    int r0 = idx % (D_DIM * KTOT);
    int nn = r0 / KTOT;
    int k  = r0 % KTOT;
    float v;
    if (k < D_DIM) {
        v = root[((size_t)l * D_DIM + k) * D_DIM + nn];
    } else {
        int kk = k - D_DIM;
        int r  = kk >> 7;
        int k2 = kk & 127;
        v = W[((((size_t)l * R_REL) + r) * D_DIM + k2) * D_DIM + nn];
    }
    __half hi = __float2half_rn(v);
    __half lo = __float2half_rn(v - __half2float(hi));
    g_Whi[l][nn][k] = hi;
    g_Wlo[l][nn][k] = lo;
}

// ---------------------------------------------------------------------------
// Counting sort of edges by key = dst*4 + rel  (3-phase parallel scan)
// ---------------------------------------------------------------------------
__global__ void hist_kernel(const int* __restrict__ edge_index,
                            const int* __restrict__ edge_type, int E)
{
    int idx = blockIdx.x * blockDim.x + threadIdx.x;
    if (idx >= E) return;
    atomicAdd(&g_cursor[edge_index[E + idx] * 4 + edge_type[idx]], 1);
}

__global__ __launch_bounds__(1024)
void scanA_kernel(int n4)
{
    __shared__ int warp_sums[32];
    const int tid  = threadIdx.x;
    const int lane = tid & 31;
    const int wrp  = tid >> 5;
    const int i    = blockIdx.x * 1024 + tid;
    int v = (i < n4) ? g_cursor[i] : 0;
    int x = v;
    #pragma unroll
    for (int d = 1; d < 32; d <<= 1) {
        int t = __shfl_up_sync(0xffffffffu, x, d);
        if (lane >= d) x += t;
    }
    if (lane == 31) warp_sums[wrp] = x;
    __syncthreads();
    if (wrp == 0) {
        int s = warp_sums[lane];
        #pragma unroll
        for (int d = 1; d < 32; d <<= 1) {
            int t = __shfl_up_sync(0xffffffffu, s, d);
            if (lane >= d) s += t;
        }
        warp_sums[lane] = s;
    }
    __syncthreads();
    int excl = x - v + (wrp ? warp_sums[wrp - 1] : 0);
    if (i < n4) g_rowstart[i] = excl;
    if (tid == 1023) g_bsum[blockIdx.x] = excl + v;
}

__global__ __launch_bounds__(256)
void scanB_kernel(int nb)
{
    __shared__ int ws[8];
    const int tid  = threadIdx.x;
    const int lane = tid & 31;
    const int wrp  = tid >> 5;
    int v = (tid < nb) ? g_bsum[tid] : 0;
    int x = v;
    #pragma unroll
    for (int d = 1; d < 32; d <<= 1) {
        int t = __shfl_up_sync(0xffffffffu, x, d);
        if (lane >= d) x += t;
    }
    if (lane == 31) ws[wrp] = x;
    __syncthreads();
    if (wrp == 0) {
        int s = (lane < 8) ? ws[lane] : 0;
        #pragma unroll
        for (int d = 1; d < 32; d <<= 1) {
            int t = __shfl_up_sync(0xffffffffu, s, d);
            if (lane >= d) s += t;
        }
        if (lane < 8) ws[lane] = s;
    }
    __syncthreads();
    int excl = x - v + (wrp ? ws[wrp - 1] : 0);
    if (tid < nb) g_bsum[tid] = excl;
}

__global__ __launch_bounds__(1024)
void scanC_kernel(int n4, int E)
{
    const int i = blockIdx.x * 1024 + threadIdx.x;
    if (i < n4) {
        int v = g_rowstart[i] + g_bsum[blockIdx.x];
        g_rowstart[i] = v;
        g_cursor[i]   = v;
    } else if (i == n4) {
        g_rowstart[n4] = E;
    }
}

__global__ void reorder_kernel(const int* __restrict__ edge_index,
                               const int* __restrict__ edge_type, int E)
{
    int idx = blockIdx.x * blockDim.x + threadIdx.x;
    if (idx >= E) return;
    int key = edge_index[E + idx] * 4 + edge_type[idx];
    int pos = atomicAdd(&g_cursor[key], 1);
    g_sorted[pos] = edge_index[idx];   // src only
}

// ---------------------------------------------------------------------------
// Kernel: CSR aggregation. One warp per dst node; fp16 in, fp32 acc, fp16 out.
// ---------------------------------------------------------------------------
__global__ __launch_bounds__(256)
void agg_kernel(const __half* __restrict__ x,
                __half* __restrict__ h, int n)
{
    int w = (blockIdx.x * blockDim.x + threadIdx.x) >> 5;
    int lane = threadIdx.x & 31;
    if (w >= n) return;

    float acc[R_REL][4];
    #pragma unroll
    for (int r = 0; r < R_REL; r++)
        #pragma unroll
        for (int j = 0; j < 4; j++) acc[r][j] = 0.f;

    int e0 = g_rowstart[w * 4];
    int e1 = g_rowstart[w * 4 + 4];
    int k0 = g_rowstart[w * 4 + 1];
    int k1 = g_rowstart[w * 4 + 2];
    int k2 = g_rowstart[w * 4 + 3];

    #pragma unroll 4
    for (int e = e0; e < e1; e++) {
        int src = __ldg(&g_sorted[e]);
        int r   = (e >= k2) ? 3 : (e >= k1) ? 2 : (e >= k0) ? 1 : 0;
        uint2 v = *reinterpret_cast<const uint2*>(x + (size_t)src * D_DIM + lane * 4);
        float2 f0 = __half22float2(*reinterpret_cast<__half2*>(&v.x));
        float2 f1 = __half22float2(*reinterpret_cast<__half2*>(&v.y));
        acc[r][0] += f0.x;
        acc[r][1] += f0.y;
        acc[r][2] += f1.x;
        acc[r][3] += f1.y;
    }

    #pragma unroll
    for (int r = 0; r < R_REL; r++) {
        size_t o = (size_t)w * (R_REL * D_DIM) + r * D_DIM + lane * 4;
        *reinterpret_cast<uint2*>(h + o) =
            make_uint2(pack2h(acc[r][0], acc[r][1]), pack2h(acc[r][2], acc[r][3]));
    }
}

// ---------------------------------------------------------------------------
// GEMM: y[m,0:128] = lrelu( [x|h][m,0:640] @ Wt^T + bias )
// A fp16 single stream; W fp16 hi+lo (2-term). CTA 128x128, 256 thr.
// cp.async 3-stage pipeline, KC=32, SW64 swizzle over 64B rows.
// ---------------------------------------------------------------------------
#define ST_A   0
#define ST_BHI 8192
#define ST_BLO 16384
#define ST_SIZE 24576
#define NSTAGE 3
#define SM_TOTAL (NSTAGE * ST_SIZE)

__global__ __launch_bounds__(256, 2)
void gemm_mma_kernel(const __half* __restrict__ x,
                     const __half* __restrict__ h,
                     const __half* __restrict__ Whi,   // [128][640]
                     const __half* __restrict__ Wlo,
                     const float* __restrict__ bias_l,
                     __half* __restrict__ yh,          // null on final
                     float* __restrict__ yf32,         // null unless final
                     int n)
{
    extern __shared__ __align__(1024) char smem[];
    const uint32_t sb = smem_u32(smem);
    const int tid    = threadIdx.x;
    const int lane   = tid & 31;
    const int wid    = tid >> 5;
    const int warp_m = wid >> 2;        // 0..1 -> 64 rows
    const int warp_n = wid & 3;         // 0..3 -> 32 cols
    const int m0     = blockIdx.x * 128;

    float acc[4][4][4];
    #pragma unroll
    for (int i = 0; i < 4; i++)
        #pragma unroll
        for (int j = 0; j < 4; j++)
            #pragma unroll
            for (int q = 0; q < 4; q++) acc[i][j][q] = 0.f;

    auto load_stage = [&](int stage, int c) {
        const __half* A;
        int lda;
        if (c < 4) { A = x + c * KC; lda = D_DIM; }
        else       { A = h + (c - 4) * KC; lda = R_REL * D_DIM; }
        const uint32_t base = sb + stage * ST_SIZE;
        #pragma unroll
        for (int it = 0; it < 2; it++) {
            int f   = it * 256 + tid;     // 0..511
            int row = f >> 2;
            int q   = f & 3;
            uint32_t off = SWZ64((uint32_t)(row * 64 + q * 16));
            int bytes = (m0 + row < n) ? 16 : 0;
            cp16z(base + ST_A + off, A + (size_t)(m0 + row) * lda + q * 8, bytes);
        }
        #pragma unroll
        for (int it = 0; it < 2; it++) {
            int f   = it * 256 + tid;
            int row = f >> 2;             // n index 0..127
            int q   = f & 3;
            uint32_t off = SWZ64((uint32_t)(row * 64 + q * 16));
            cp16(base + ST_BHI + off, Whi + (size_t)row * KTOT + c * KC + q * 8);
            cp16(base + ST_BLO + off, Wlo + (size_t)row * KTOT + c * KC + q * 8);
        }
    };

    // Prologue: fill stages 0 and 1.
    load_stage(0, 0);
    CP_COMMIT();
    load_stage(1, 1);
    CP_COMMIT();

    int stage = 0;
    for (int c = 0; c < NCHUNK; c++) {
        // Issue load for c+2 into the stage freed at iteration c-1.
        // The trailing __syncthreads of iteration c-1 guarantees all warps
        // finished reading that stage.
        if (c + 2 < NCHUNK) {
            load_stage((stage + 2) % NSTAGE, c + 2);
            CP_COMMIT();
            CP_WAIT(2);           // groups c+1, c+2 may remain in flight
        } else if (c + 1 < NCHUNK) {
            CP_WAIT(1);           // group c+1 may remain
        } else {
            CP_WAIT(0);
        }
        __syncthreads();

        const uint32_t base = sb + stage * ST_SIZE;
        #pragma unroll
        for (int ks = 0; ks < 2; ks++) {
            const int k0 = ks * 16;
            uint32_t bh[2][4], bl[2][4];
            #pragma unroll
            for (int p = 0; p < 2; p++) {
                int nb   = warp_n * 32 + p * 16;
                int row  = nb + (lane & 7) + ((lane >> 4) << 3);
                uint32_t off = SWZ64((uint32_t)(row * 64 + k0 * 2 + ((lane & 8) ? 16 : 0)));
                ldmatrix_x4(bh[p][0], bh[p][1], bh[p][2], bh[p][3], base + ST_BHI + off);
                ldmatrix_x4(bl[p][0], bl[p][1], bl[p][2], bl[p][3], base + ST_BLO + off);
            }
            #pragma unroll
            for (int m = 0; m < 4; m++) {
                int row  = warp_m * 64 + m * 16 + (lane & 15);
                uint32_t off = SWZ64((uint32_t)(row * 64 + k0 * 2 + ((lane >> 4) << 4)));
                uint32_t a[4];
                ldmatrix_x4(a[0], a[1], a[2], a[3], base + ST_A + off);
                #pragma unroll
                for (int p = 0; p < 2; p++) {
                    #pragma unroll
                    for (int t = 0; t < 2; t++) {
                        int nt = p * 2 + t;
                        mma_f16(acc[m][nt], a, bh[p][t * 2], bh[p][t * 2 + 1]);
                        mma_f16(acc[m][nt], a, bl[p][t * 2], bl[p][t * 2 + 1]);
                    }
                }
            }
        }
        __syncthreads();
        stage = (stage + 1) % NSTAGE;
    }

    // ---- epilogue: bias + leaky_relu ----
    #pragma unroll
    for (int nt = 0; nt < 4; nt++) {
        int col = warp_n * 32 + nt * 8 + (lane & 3) * 2;
        float2 b = *reinterpret_cast<const float2*>(bias_l + col);
        #pragma unroll
        for (int m = 0; m < 4; m++) {
            int row0 = m0 + warp_m * 64 + m * 16 + (lane >> 2);
            #pragma unroll
            for (int half = 0; half < 2; half++) {
                int row = row0 + half * 8;
                if (row < n) {
                    float v0 = acc[m][nt][half * 2 + 0] + b.x;
                    float v1 = acc[m][nt][half * 2 + 1] + b.y;
                    v0 = v0 > 0.f ? v0 : 0.01f * v0;
                    v1 = v1 > 0.f ? v1 : 0.01f * v1;
                    if (yf32) {
                        *reinterpret_cast<float2*>(yf32 + (size_t)row * D_DIM + col) =
                            make_float2(v0, v1);
                    } else {
                        *reinterpret_cast<uint32_t*>(yh + (size_t)row * D_DIM + col) =
                            pack2h(v0, v1);
                    }
                }
            }
        }
    }
}

// ---------------------------------------------------------------------------
// Launch
// ---------------------------------------------------------------------------
extern "C" void kernel_launch(void* const* d_in, const int* in_sizes, int n_in,
                              void* d_out, int out_size)
{
    const int*   node_type  = (const int*)  d_in[0];
    const int*   edge_index = (const int*)  d_in[1];
    const int*   edge_type  = (const int*)  d_in[2];
    const float* emb        = (const float*)d_in[3];
    const float* W          = (const float*)d_in[4];   // [L,R,D,D]
    const float* root       = (const float*)d_in[5];   // [L,D,D]
    const float* bias       = (const float*)d_in[6];   // [L,D]
    float*       out        = (float*)d_out;

    const int n  = in_sizes[0];
    const int E  = in_sizes[2];
    const int n4 = n * R_REL;

    __half *xA, *xB, *h, *whi, *wlo;
    int* cursor;
    cudaGetSymbolAddress((void**)&xA,  g_xA);
    cudaGetSymbolAddress((void**)&xB,  g_xB);
    cudaGetSymbolAddress((void**)&h,   g_h);
    cudaGetSymbolAddress((void**)&whi, g_Whi);
    cudaGetSymbolAddress((void**)&wlo, g_Wlo);
    cudaGetSymbolAddress((void**)&cursor, g_cursor);

    cudaFuncSetAttribute(gemm_mma_kernel,
                         cudaFuncAttributeMaxDynamicSharedMemorySize, SM_TOTAL);

    // --- one-time per launch: embed, weight prep, edge sort ---
    cudaMemsetAsync(cursor, 0, (size_t)n4 * sizeof(int));
    embed_kernel<<<(n * 32 + 255) / 256, 256>>>(node_type, emb, xA, n);
    {
        const int TOT = L_LAY * D_DIM * KTOT;
        prep_kernel<<<(TOT + 255) / 256, 256>>>(W, root);
    }
    hist_kernel<<<(E + 255) / 256, 256>>>(edge_index, edge_type, E);
    {
        const int nb = (n4 + 1023) / 1024;
        scanA_kernel<<<nb, 1024>>>(n4);
        scanB_kernel<<<1, 256>>>(nb);
        scanC_kernel<<<(n4 + 1 + 1023) / 1024, 1024>>>(n4, E);
    }
    reorder_kernel<<<(E + 255) / 256, 256>>>(edge_index, edge_type, E);

    const int agg_blocks  = (n * 32 + 255) / 256;
    const int gemm_blocks = (n + 127) / 128;

    for (int l = 0; l < L_LAY; l++) {
        const __half* xin = (l == 1) ? xB : xA;
        __half*       xout = (l == 0) ? xB : xA;

        agg_kernel<<<agg_blocks, 256>>>(xin, h, n);

        if (l < L_LAY - 1) {
            gemm_mma_kernel<<<gemm_blocks, 256, SM_TOTAL>>>(
                xin, h,
                whi + (size_t)l * D_DIM * KTOT,
                wlo + (size_t)l * D_DIM * KTOT,
                bias + (size_t)l * D_DIM,
                xout, (float*)nullptr, n);
        } else {
            gemm_mma_kernel<<<gemm_blocks, 256, SM_TOTAL>>>(
                xin, h,
                whi + (size_t)l * D_DIM * KTOT,
                wlo + (size_t)l * D_DIM * KTOT,
                bias + (size_t)l * D_DIM,
                (__half*)nullptr, out, n);
        }
    }
}

// round 11
// speedup vs baseline: 1.6390x; 1.0258x over previous
#include <cuda_runtime.h>
#include <cuda_fp16.h>
#include <cstdint>

#define N_NODES 50000
#define E_MAX   600000
#define D_DIM   128
#define R_REL   4
#define L_LAY   3
#define KTOT    640           // 128 (root) + 4*128 (W)
#define KC      64            // K per pipeline stage
#define NCHUNK  (KTOT / KC)   // 10
#define NR4     (N_NODES * R_REL)

// ---------------------------------------------------------------------------
// Static device scratch (no runtime allocation allowed)
// ---------------------------------------------------------------------------
__device__ __half g_xA[(size_t)N_NODES * D_DIM];
__device__ __half g_xB[(size_t)N_NODES * D_DIM];
__device__ __half g_h [(size_t)N_NODES * R_REL * D_DIM];
// Transposed + fp16-split stacked weights: Bt[l][n][k], k in [0,640)
__device__ __half g_Whi[L_LAY][D_DIM][KTOT];
__device__ __half g_Wlo[L_LAY][D_DIM][KTOT];
// Edge sort (key = dst*4 + relation)
__device__ int g_sorted[E_MAX];
__device__ int g_rowstart[NR4 + 1];
__device__ int g_cursor[NR4];
__device__ int g_bsum[256];

// ---------------------------------------------------------------------------
// Helpers
// ---------------------------------------------------------------------------
#define SWZ128(off) ((off) ^ (((off) >> 3) & 0x70))

__device__ __forceinline__ uint32_t smem_u32(const void* p) {
    uint32_t a;
    asm("{ .reg .u64 t; cvta.to.shared.u64 t, %1; cvt.u32.u64 %0, t; }"
        : "=r"(a) : "l"(p));
    return a;
}
__device__ __forceinline__ void cp16(uint32_t d, const void* s) {
    asm volatile("cp.async.cg.shared.global [%0], [%1], 16;" :: "r"(d), "l"(s));
}
__device__ __forceinline__ void cp16z(uint32_t d, const void* s, int bytes) {
    asm volatile("cp.async.cg.shared.global [%0], [%1], 16, %2;"
                 :: "r"(d), "l"(s), "r"(bytes));
}
#define CP_COMMIT() asm volatile("cp.async.commit_group;" ::: "memory")
#define CP_WAIT(N)  asm volatile("cp.async.wait_group %0;" :: "n"(N) : "memory")

__device__ __forceinline__ void ldmatrix_x4(uint32_t& r0, uint32_t& r1,
                                            uint32_t& r2, uint32_t& r3,
                                            uint32_t addr) {
    asm volatile("ldmatrix.sync.aligned.m8n8.x4.shared.b16 {%0,%1,%2,%3}, [%4];"
                 : "=r"(r0), "=r"(r1), "=r"(r2), "=r"(r3) : "r"(addr));
}
__device__ __forceinline__ void mma_f16(float* c, const uint32_t* a,
                                        uint32_t b0, uint32_t b1) {
    asm volatile(
        "mma.sync.aligned.m16n8k16.row.col.f32.f16.f16.f32 "
        "{%0,%1,%2,%3}, {%4,%5,%6,%7}, {%8,%9}, {%0,%1,%2,%3};"
        : "+f"(c[0]), "+f"(c[1]), "+f"(c[2]), "+f"(c[3])
        : "r"(a[0]), "r"(a[1]), "r"(a[2]), "r"(a[3]), "r"(b0), "r"(b1));
}

__device__ __forceinline__ uint32_t pack2h(float a, float b) {
    __half2 h = __floats2half2_rn(a, b);
    return *reinterpret_cast<uint32_t*>(&h);
}

// ---------------------------------------------------------------------------
// Kernel: embed -> fp16  AND weight prep (merged; disjoint index ranges)
// ---------------------------------------------------------------------------
__global__ void embedprep_kernel(const int* __restrict__ node_type,
                                 const float* __restrict__ emb,
                                 __half* __restrict__ x,
                                 const float* __restrict__ W,
                                 const float* __restrict__ root, int n)
{
    const int nEmb = n * 32;
    const int TOT  = L_LAY * D_DIM * KTOT;
    int idx = blockIdx.x * blockDim.x + threadIdx.x;
    if (idx < nEmb) {
        int node = idx >> 5;
        int q    = idx & 31;
        float4 v = reinterpret_cast<const float4*>(emb + (size_t)node_type[node] * D_DIM)[q];
        *reinterpret_cast<uint2*>(x + (size_t)node * D_DIM + q * 4) =
            make_uint2(pack2h(v.x, v.y), pack2h(v.z, v.w));
        return;
    }
    idx -= nEmb;
    if (idx >= TOT) return;
    int l  = idx / (D_DIM * KTOT);
    int r0 = idx % (D_DIM * KTOT);
    int nn = r0 / KTOT;
    int k  = r0 % KTOT;
    float v;
    if (k < D_DIM) {
        v = root[((size_t)l * D_DIM + k) * D_DIM + nn];
    } else {
        int kk = k - D_DIM;
        int r  = kk >> 7;
        int k2 = kk & 127;
        v = W[((((size_t)l * R_REL) + r) * D_DIM + k2) * D_DIM + nn];
    }
    __half hi = __float2half_rn(v);
    __half lo = __float2half_rn(v - __half2float(hi));
    g_Whi[l][nn][k] = hi;
    g_Wlo[l][nn][k] = lo;
}

// ---------------------------------------------------------------------------
// Counting sort of edges by key = dst*4 + rel  (3-phase parallel scan)
// ---------------------------------------------------------------------------
__global__ void hist_kernel(const int* __restrict__ edge_index,
                            const int* __restrict__ edge_type, int E)
{
    int idx = blockIdx.x * blockDim.x + threadIdx.x;
    if (idx >= E) return;
    atomicAdd(&g_cursor[edge_index[E + idx] * 4 + edge_type[idx]], 1);
}

__global__ __launch_bounds__(1024)
void scanA_kernel(int n4)
{
    __shared__ int warp_sums[32];
    const int tid  = threadIdx.x;
    const int lane = tid & 31;
    const int wrp  = tid >> 5;
    const int i    = blockIdx.x * 1024 + tid;
    int v = (i < n4) ? g_cursor[i] : 0;
    int x = v;
    #pragma unroll
    for (int d = 1; d < 32; d <<= 1) {
        int t = __shfl_up_sync(0xffffffffu, x, d);
        if (lane >= d) x += t;
    }
    if (lane == 31) warp_sums[wrp] = x;
    __syncthreads();
    if (wrp == 0) {
        int s = warp_sums[lane];
        #pragma unroll
        for (int d = 1; d < 32; d <<= 1) {
            int t = __shfl_up_sync(0xffffffffu, s, d);
            if (lane >= d) s += t;
        }
        warp_sums[lane] = s;
    }
    __syncthreads();
    int excl = x - v + (wrp ? warp_sums[wrp - 1] : 0);
    if (i < n4) g_rowstart[i] = excl;
    if (tid == 1023) g_bsum[blockIdx.x] = excl + v;
}

__global__ __launch_bounds__(256)
void scanB_kernel(int nb)
{
    __shared__ int ws[8];
    const int tid  = threadIdx.x;
    const int lane = tid & 31;
    const int wrp  = tid >> 5;
    int v = (tid < nb) ? g_bsum[tid] : 0;
    int x = v;
    #pragma unroll
    for (int d = 1; d < 32; d <<= 1) {
        int t = __shfl_up_sync(0xffffffffu, x, d);
        if (lane >= d) x += t;
    }
    if (lane == 31) ws[wrp] = x;
    __syncthreads();
    if (wrp == 0) {
        int s = (lane < 8) ? ws[lane] : 0;
        #pragma unroll
        for (int d = 1; d < 32; d <<= 1) {
            int t = __shfl_up_sync(0xffffffffu, s, d);
            if (lane >= d) s += t;
        }
        if (lane < 8) ws[lane] = s;
    }
    __syncthreads();
    int excl = x - v + (wrp ? ws[wrp - 1] : 0);
    if (tid < nb) g_bsum[tid] = excl;
}

__global__ __launch_bounds__(1024)
void scanC_kernel(int n4, int E)
{
    const int i = blockIdx.x * 1024 + threadIdx.x;
    if (i < n4) {
        int v = g_rowstart[i] + g_bsum[blockIdx.x];
        g_rowstart[i] = v;
        g_cursor[i]   = v;
    } else if (i == n4) {
        g_rowstart[n4] = E;
    }
}

__global__ void reorder_kernel(const int* __restrict__ edge_index,
                               const int* __restrict__ edge_type, int E)
{
    int idx = blockIdx.x * blockDim.x + threadIdx.x;
    if (idx >= E) return;
    int key = edge_index[E + idx] * 4 + edge_type[idx];
    int pos = atomicAdd(&g_cursor[key], 1);
    g_sorted[pos] = edge_index[idx];   // src only
}

// ---------------------------------------------------------------------------
// Kernel: CSR aggregation. One warp per dst node; fp16 in, fp32 acc, fp16 out.
// ---------------------------------------------------------------------------
__global__ __launch_bounds__(256)
void agg_kernel(const __half* __restrict__ x,
                __half* __restrict__ h, int n)
{
    int w = (blockIdx.x * blockDim.x + threadIdx.x) >> 5;
    int lane = threadIdx.x & 31;
    if (w >= n) return;

    float acc[R_REL][4];
    #pragma unroll
    for (int r = 0; r < R_REL; r++)
        #pragma unroll
        for (int j = 0; j < 4; j++) acc[r][j] = 0.f;

    int e0 = g_rowstart[w * 4];
    int e1 = g_rowstart[w * 4 + 4];
    int k0 = g_rowstart[w * 4 + 1];
    int k1 = g_rowstart[w * 4 + 2];
    int k2 = g_rowstart[w * 4 + 3];

    #pragma unroll 4
    for (int e = e0; e < e1; e++) {
        int src = __ldg(&g_sorted[e]);
        int r   = (e >= k2) ? 3 : (e >= k1) ? 2 : (e >= k0) ? 1 : 0;
        uint2 v = *reinterpret_cast<const uint2*>(x + (size_t)src * D_DIM + lane * 4);
        float2 f0 = __half22float2(*reinterpret_cast<__half2*>(&v.x));
        float2 f1 = __half22float2(*reinterpret_cast<__half2*>(&v.y));
        acc[r][0] += f0.x;
        acc[r][1] += f0.y;
        acc[r][2] += f1.x;
        acc[r][3] += f1.y;
    }

    #pragma unroll
    for (int r = 0; r < R_REL; r++) {
        size_t o = (size_t)w * (R_REL * D_DIM) + r * D_DIM + lane * 4;
        *reinterpret_cast<uint2*>(h + o) =
            make_uint2(pack2h(acc[r][0], acc[r][1]), pack2h(acc[r][2], acc[r][3]));
    }
}

// ---------------------------------------------------------------------------
// GEMM: y[m,0:128] = lrelu( [x|h][m,0:640] @ Wt^T + bias )
// A fp16 single stream; W fp16 hi+lo (2-term). CTA 128x128, 256 thr.
// cp.async 2-stage pipeline, KC=64 (4 unrolled k16-steps per chunk),
// 128-byte rows + SW128 swizzle.
// ---------------------------------------------------------------------------
#define ST_A   0
#define ST_BHI 16384
#define ST_BLO 32768
#define ST_SIZE 49152
#define SM_TOTAL (2 * ST_SIZE)

__global__ __launch_bounds__(256, 2)
void gemm_mma_kernel(const __half* __restrict__ x,
                     const __half* __restrict__ h,
                     const __half* __restrict__ Whi,   // [128][640]
                     const __half* __restrict__ Wlo,
                     const float* __restrict__ bias_l,
                     __half* __restrict__ yh,          // null on final
                     float* __restrict__ yf32,         // null unless final
                     int n)
{
    extern __shared__ __align__(1024) char smem[];
    const uint32_t sb = smem_u32(smem);
    const int tid    = threadIdx.x;
    const int lane   = tid & 31;
    const int wid    = tid >> 5;
    const int warp_m = wid >> 2;        // 0..1 -> 64 rows
    const int warp_n = wid & 3;         // 0..3 -> 32 cols
    const int m0     = blockIdx.x * 128;

    float acc[4][4][4];
    #pragma unroll
    for (int i = 0; i < 4; i++)
        #pragma unroll
        for (int j = 0; j < 4; j++)
            #pragma unroll
            for (int q = 0; q < 4; q++) acc[i][j][q] = 0.f;

    auto load_stage = [&](int stage, int c) {
        const __half* A;
        int lda;
        if (c < 2) { A = x + c * KC; lda = D_DIM; }
        else       { A = h + (c - 2) * KC; lda = R_REL * D_DIM; }
        const uint32_t base = sb + stage * ST_SIZE;
        // A: 128 rows x 64 fp16 = 1024 16B-granules
        #pragma unroll
        for (int it = 0; it < 4; it++) {
            int f   = it * 256 + tid;
            int row = f >> 3;
            int q   = f & 7;
            uint32_t off = SWZ128((uint32_t)(row * 128 + q * 16));
            int bytes = (m0 + row < n) ? 16 : 0;
            cp16z(base + ST_A + off, A + (size_t)(m0 + row) * lda + q * 8, bytes);
        }
        // B hi/lo: 128 rows x 64 fp16 each
        #pragma unroll
        for (int it = 0; it < 4; it++) {
            int f   = it * 256 + tid;
            int row = f >> 3;
            int q   = f & 7;
            uint32_t off = SWZ128((uint32_t)(row * 128 + q * 16));
            cp16(base + ST_BHI + off, Whi + (size_t)row * KTOT + c * KC + q * 8);
            cp16(base + ST_BLO + off, Wlo + (size_t)row * KTOT + c * KC + q * 8);
        }
    };

    load_stage(0, 0);
    CP_COMMIT();

    for (int c = 0; c < NCHUNK; c++) {
        if (c + 1 < NCHUNK) {
            load_stage((c + 1) & 1, c + 1);
            CP_COMMIT();
            CP_WAIT(1);
        } else {
            CP_WAIT(0);
        }
        __syncthreads();

        const uint32_t base = sb + (c & 1) * ST_SIZE;
        #pragma unroll
        for (int ks = 0; ks < 4; ks++) {
            const int k0 = ks * 16;
            uint32_t bh[2][4], bl[2][4];
            #pragma unroll
            for (int p = 0; p < 2; p++) {
                int nb   = warp_n * 32 + p * 16;
                int row  = nb + (lane & 7) + ((lane >> 4) << 3);
                uint32_t off = SWZ128((uint32_t)(row * 128 + k0 * 2 + ((lane & 8) ? 16 : 0)));
                ldmatrix_x4(bh[p][0], bh[p][1], bh[p][2], bh[p][3], base + ST_BHI + off);
                ldmatrix_x4(bl[p][0], bl[p][1], bl[p][2], bl[p][3], base + ST_BLO + off);
            }
            #pragma unroll
            for (int m = 0; m < 4; m++) {
                int row  = warp_m * 64 + m * 16 + (lane & 15);
                uint32_t off = SWZ128((uint32_t)(row * 128 + k0 * 2 + ((lane >> 4) << 4)));
                uint32_t a[4];
                ldmatrix_x4(a[0], a[1], a[2], a[3], base + ST_A + off);
                #pragma unroll
                for (int p = 0; p < 2; p++) {
                    #pragma unroll
                    for (int t = 0; t < 2; t++) {
                        int nt = p * 2 + t;
                        mma_f16(acc[m][nt], a, bh[p][t * 2], bh[p][t * 2 + 1]);
                        mma_f16(acc[m][nt], a, bl[p][t * 2], bl[p][t * 2 + 1]);
                    }
                }
            }
        }
        __syncthreads();
    }

    // ---- epilogue: bias + leaky_relu ----
    #pragma unroll
    for (int nt = 0; nt < 4; nt++) {
        int col = warp_n * 32 + nt * 8 + (lane & 3) * 2;
        float2 b = *reinterpret_cast<const float2*>(bias_l + col);
        #pragma unroll
        for (int m = 0; m < 4; m++) {
            int row0 = m0 + warp_m * 64 + m * 16 + (lane >> 2);
            #pragma unroll
            for (int half = 0; half < 2; half++) {
                int row = row0 + half * 8;
                if (row < n) {
                    float v0 = acc[m][nt][half * 2 + 0] + b.x;
                    float v1 = acc[m][nt][half * 2 + 1] + b.y;
                    v0 = v0 > 0.f ? v0 : 0.01f * v0;
                    v1 = v1 > 0.f ? v1 : 0.01f * v1;
                    if (yf32) {
                        *reinterpret_cast<float2*>(yf32 + (size_t)row * D_DIM + col) =
                            make_float2(v0, v1);
                    } else {
                        *reinterpret_cast<uint32_t*>(yh + (size_t)row * D_DIM + col) =
                            pack2h(v0, v1);
                    }
                }
            }
        }
    }
}

// ---------------------------------------------------------------------------
// Launch
// ---------------------------------------------------------------------------
extern "C" void kernel_launch(void* const* d_in, const int* in_sizes, int n_in,
                              void* d_out, int out_size)
{
    const int*   node_type  = (const int*)  d_in[0];
    const int*   edge_index = (const int*)  d_in[1];
    const int*   edge_type  = (const int*)  d_in[2];
    const float* emb        = (const float*)d_in[3];
    const float* W          = (const float*)d_in[4];   // [L,R,D,D]
    const float* root       = (const float*)d_in[5];   // [L,D,D]
    const float* bias       = (const float*)d_in[6];   // [L,D]
    float*       out        = (float*)d_out;

    const int n  = in_sizes[0];
    const int E  = in_sizes[2];
    const int n4 = n * R_REL;

    __half *xA, *xB, *h, *whi, *wlo;
    int* cursor;
    cudaGetSymbolAddress((void**)&xA,  g_xA);
    cudaGetSymbolAddress((void**)&xB,  g_xB);
    cudaGetSymbolAddress((void**)&h,   g_h);
    cudaGetSymbolAddress((void**)&whi, g_Whi);
    cudaGetSymbolAddress((void**)&wlo, g_Wlo);
    cudaGetSymbolAddress((void**)&cursor, g_cursor);

    cudaFuncSetAttribute(gemm_mma_kernel,
                         cudaFuncAttributeMaxDynamicSharedMemorySize, SM_TOTAL);

    // --- one-time per launch: embed+prep, edge sort ---
    cudaMemsetAsync(cursor, 0, (size_t)n4 * sizeof(int));
    {
        const int TOT   = L_LAY * D_DIM * KTOT;
        const int total = n * 32 + TOT;
        embedprep_kernel<<<(total + 255) / 256, 256>>>(node_type, emb, xA, W, root, n);
    }
    hist_kernel<<<(E + 255) / 256, 256>>>(edge_index, edge_type, E);
    {
        const int nb = (n4 + 1023) / 1024;
        scanA_kernel<<<nb, 1024>>>(n4);
        scanB_kernel<<<1, 256>>>(nb);
        scanC_kernel<<<(n4 + 1 + 1023) / 1024, 1024>>>(n4, E);
    }
    reorder_kernel<<<(E + 255) / 256, 256>>>(edge_index, edge_type, E);

    const int agg_blocks  = (n * 32 + 255) / 256;
    const int gemm_blocks = (n + 127) / 128;

    for (int l = 0; l < L_LAY; l++) {
        const __half* xin = (l == 1) ? xB : xA;
        __half*       xout = (l == 0) ? xB : xA;

        agg_kernel<<<agg_blocks, 256>>>(xin, h, n);

        if (l < L_LAY - 1) {
            gemm_mma_kernel<<<gemm_blocks, 256, SM_TOTAL>>>(
                xin, h,
                whi + (size_t)l * D_DIM * KTOT,
                wlo + (size_t)l * D_DIM * KTOT,
                bias + (size_t)l * D_DIM,
                xout, (float*)nullptr, n);
        } else {
            gemm_mma_kernel<<<gemm_blocks, 256, SM_TOTAL>>>(
                xin, h,
                whi + (size_t)l * D_DIM * KTOT,
                wlo + (size_t)l * D_DIM * KTOT,
                bias + (size_t)l * D_DIM,
                (__half*)nullptr, out, n);
        }
    }
}

// round 12
// speedup vs baseline: 2.0591x; 1.2563x over previous
#include <cuda_runtime.h>
#include <cuda_fp16.h>
#include <cstdint>

#define N_NODES 50000
#define E_MAX   600000
#define D_DIM   128
#define R_REL   4
#define L_LAY   3
#define KTOT    640           // 128 (root) + 4*128 (W)
#define KC      64            // K per pipeline stage
#define NCHUNK  (KTOT / KC)   // 10
#define NR4     (N_NODES * R_REL)

// ---------------------------------------------------------------------------
// Static device scratch (no runtime allocation allowed)
// ---------------------------------------------------------------------------
__device__ __half g_xA[(size_t)N_NODES * D_DIM];
__device__ __half g_xB[(size_t)N_NODES * D_DIM];
__device__ __half g_h [(size_t)N_NODES * R_REL * D_DIM];
// Transposed fp16 stacked weights: Wt[l][n][k], k in [0,640)
__device__ __half g_Wt[L_LAY][D_DIM][KTOT];
// Edge sort (key = dst*4 + relation)
__device__ int g_sorted[E_MAX];
__device__ int g_rowstart[NR4 + 1];
__device__ int g_cursor[NR4];
__device__ int g_bsum[256];

// ---------------------------------------------------------------------------
// Helpers
// ---------------------------------------------------------------------------
#define SWZ128(off) ((off) ^ (((off) >> 3) & 0x70))

__device__ __forceinline__ uint32_t smem_u32(const void* p) {
    uint32_t a;
    asm("{ .reg .u64 t; cvta.to.shared.u64 t, %1; cvt.u32.u64 %0, t; }"
        : "=r"(a) : "l"(p));
    return a;
}
__device__ __forceinline__ void cp16(uint32_t d, const void* s) {
    asm volatile("cp.async.cg.shared.global [%0], [%1], 16;" :: "r"(d), "l"(s));
}
__device__ __forceinline__ void cp16z(uint32_t d, const void* s, int bytes) {
    asm volatile("cp.async.cg.shared.global [%0], [%1], 16, %2;"
                 :: "r"(d), "l"(s), "r"(bytes));
}
#define CP_COMMIT() asm volatile("cp.async.commit_group;" ::: "memory")
#define CP_WAIT(N)  asm volatile("cp.async.wait_group %0;" :: "n"(N) : "memory")

__device__ __forceinline__ void ldmatrix_x4(uint32_t& r0, uint32_t& r1,
                                            uint32_t& r2, uint32_t& r3,
                                            uint32_t addr) {
    asm volatile("ldmatrix.sync.aligned.m8n8.x4.shared.b16 {%0,%1,%2,%3}, [%4];"
                 : "=r"(r0), "=r"(r1), "=r"(r2), "=r"(r3) : "r"(addr));
}
__device__ __forceinline__ void mma_f16(float* c, const uint32_t* a,
                                        uint32_t b0, uint32_t b1) {
    asm volatile(
        "mma.sync.aligned.m16n8k16.row.col.f32.f16.f16.f32 "
        "{%0,%1,%2,%3}, {%4,%5,%6,%7}, {%8,%9}, {%0,%1,%2,%3};"
        : "+f"(c[0]), "+f"(c[1]), "+f"(c[2]), "+f"(c[3])
        : "r"(a[0]), "r"(a[1]), "r"(a[2]), "r"(a[3]), "r"(b0), "r"(b1));
}

__device__ __forceinline__ uint32_t pack2h(float a, float b) {
    __half2 h = __floats2half2_rn(a, b);
    return *reinterpret_cast<uint32_t*>(&h);
}

// ---------------------------------------------------------------------------
// Kernel: embed -> fp16  AND weight prep (merged; disjoint index ranges)
// ---------------------------------------------------------------------------
__global__ void embedprep_kernel(const int* __restrict__ node_type,
                                 const float* __restrict__ emb,
                                 __half* __restrict__ x,
                                 const float* __restrict__ W,
                                 const float* __restrict__ root, int n)
{
    const int nEmb = n * 32;
    const int TOT  = L_LAY * D_DIM * KTOT;
    int idx = blockIdx.x * blockDim.x + threadIdx.x;
    if (idx < nEmb) {
        int node = idx >> 5;
        int q    = idx & 31;
        float4 v = reinterpret_cast<const float4*>(emb + (size_t)node_type[node] * D_DIM)[q];
        *reinterpret_cast<uint2*>(x + (size_t)node * D_DIM + q * 4) =
            make_uint2(pack2h(v.x, v.y), pack2h(v.z, v.w));
        return;
    }
    idx -= nEmb;
    if (idx >= TOT) return;
    int l  = idx / (D_DIM * KTOT);
    int r0 = idx % (D_DIM * KTOT);
    int nn = r0 / KTOT;
    int k  = r0 % KTOT;
    float v;
    if (k < D_DIM) {
        v = root[((size_t)l * D_DIM + k) * D_DIM + nn];
    } else {
        int kk = k - D_DIM;
        int r  = kk >> 7;
        int k2 = kk & 127;
        v = W[((((size_t)l * R_REL) + r) * D_DIM + k2) * D_DIM + nn];
    }
    g_Wt[l][nn][k] = __float2half_rn(v);
}

// ---------------------------------------------------------------------------
// Counting sort of edges by key = dst*4 + rel  (3-phase parallel scan)
// ---------------------------------------------------------------------------
__global__ void hist_kernel(const int* __restrict__ edge_index,
                            const int* __restrict__ edge_type, int E)
{
    int idx = blockIdx.x * blockDim.x + threadIdx.x;
    if (idx >= E) return;
    atomicAdd(&g_cursor[edge_index[E + idx] * 4 + edge_type[idx]], 1);
}

__global__ __launch_bounds__(1024)
void scanA_kernel(int n4)
{
    __shared__ int warp_sums[32];
    const int tid  = threadIdx.x;
    const int lane = tid & 31;
    const int wrp  = tid >> 5;
    const int i    = blockIdx.x * 1024 + tid;
    int v = (i < n4) ? g_cursor[i] : 0;
    int x = v;
    #pragma unroll
    for (int d = 1; d < 32; d <<= 1) {
        int t = __shfl_up_sync(0xffffffffu, x, d);
        if (lane >= d) x += t;
    }
    if (lane == 31) warp_sums[wrp] = x;
    __syncthreads();
    if (wrp == 0) {
        int s = warp_sums[lane];
        #pragma unroll
        for (int d = 1; d < 32; d <<= 1) {
            int t = __shfl_up_sync(0xffffffffu, s, d);
            if (lane >= d) s += t;
        }
        warp_sums[lane] = s;
    }
    __syncthreads();
    int excl = x - v + (wrp ? warp_sums[wrp - 1] : 0);
    if (i < n4) g_rowstart[i] = excl;
    if (tid == 1023) g_bsum[blockIdx.x] = excl + v;
}

__global__ __launch_bounds__(256)
void scanB_kernel(int nb)
{
    __shared__ int ws[8];
    const int tid  = threadIdx.x;
    const int lane = tid & 31;
    const int wrp  = tid >> 5;
    int v = (tid < nb) ? g_bsum[tid] : 0;
    int x = v;
    #pragma unroll
    for (int d = 1; d < 32; d <<= 1) {
        int t = __shfl_up_sync(0xffffffffu, x, d);
        if (lane >= d) x += t;
    }
    if (lane == 31) ws[wrp] = x;
    __syncthreads();
    if (wrp == 0) {
        int s = (lane < 8) ? ws[lane] : 0;
        #pragma unroll
        for (int d = 1; d < 32; d <<= 1) {
            int t = __shfl_up_sync(0xffffffffu, s, d);
            if (lane >= d) s += t;
        }
        if (lane < 8) ws[lane] = s;
    }
    __syncthreads();
    int excl = x - v + (wrp ? ws[wrp - 1] : 0);
    if (tid < nb) g_bsum[tid] = excl;
}

__global__ __launch_bounds__(1024)
void scanC_kernel(int n4, int E)
{
    const int i = blockIdx.x * 1024 + threadIdx.x;
    if (i < n4) {
        int v = g_rowstart[i] + g_bsum[blockIdx.x];
        g_rowstart[i] = v;
        g_cursor[i]   = v;
    } else if (i == n4) {
        g_rowstart[n4] = E;
    }
}

__global__ void reorder_kernel(const int* __restrict__ edge_index,
                               const int* __restrict__ edge_type, int E)
{
    int idx = blockIdx.x * blockDim.x + threadIdx.x;
    if (idx >= E) return;
    int key = edge_index[E + idx] * 4 + edge_type[idx];
    int pos = atomicAdd(&g_cursor[key], 1);
    g_sorted[pos] = edge_index[idx];   // src only
}

// ---------------------------------------------------------------------------
// Kernel: CSR aggregation. One warp per dst node; fp16 in, fp32 acc, fp16 out.
// ---------------------------------------------------------------------------
__global__ __launch_bounds__(256)
void agg_kernel(const __half* __restrict__ x,
                __half* __restrict__ h, int n)
{
    int w = (blockIdx.x * blockDim.x + threadIdx.x) >> 5;
    int lane = threadIdx.x & 31;
    if (w >= n) return;

    float acc[R_REL][4];
    #pragma unroll
    for (int r = 0; r < R_REL; r++)
        #pragma unroll
        for (int j = 0; j < 4; j++) acc[r][j] = 0.f;

    int e0 = g_rowstart[w * 4];
    int e1 = g_rowstart[w * 4 + 4];
    int k0 = g_rowstart[w * 4 + 1];
    int k1 = g_rowstart[w * 4 + 2];
    int k2 = g_rowstart[w * 4 + 3];

    #pragma unroll 4
    for (int e = e0; e < e1; e++) {
        int src = __ldg(&g_sorted[e]);
        int r   = (e >= k2) ? 3 : (e >= k1) ? 2 : (e >= k0) ? 1 : 0;
        uint2 v = *reinterpret_cast<const uint2*>(x + (size_t)src * D_DIM + lane * 4);
        float2 f0 = __half22float2(*reinterpret_cast<__half2*>(&v.x));
        float2 f1 = __half22float2(*reinterpret_cast<__half2*>(&v.y));
        acc[r][0] += f0.x;
        acc[r][1] += f0.y;
        acc[r][2] += f1.x;
        acc[r][3] += f1.y;
    }

    #pragma unroll
    for (int r = 0; r < R_REL; r++) {
        size_t o = (size_t)w * (R_REL * D_DIM) + r * D_DIM + lane * 4;
        *reinterpret_cast<uint2*>(h + o) =
            make_uint2(pack2h(acc[r][0], acc[r][1]), pack2h(acc[r][2], acc[r][3]));
    }
}

// ---------------------------------------------------------------------------
// GEMM: y[m,0:128] = lrelu( [x|h][m,0:640] @ Wt^T + bias )
// A fp16 single stream; W fp16 single term. CTA 128x128, 256 thr.
// cp.async 2-stage pipeline, KC=64 (4 unrolled k16-steps per chunk),
// 128-byte rows + SW128 swizzle.
// ---------------------------------------------------------------------------
#define ST_A   0
#define ST_B   16384
#define ST_SIZE 32768
#define SM_TOTAL (2 * ST_SIZE)

__global__ __launch_bounds__(256, 2)
void gemm_mma_kernel(const __half* __restrict__ x,
                     const __half* __restrict__ h,
                     const __half* __restrict__ Wt,    // [128][640]
                     const float* __restrict__ bias_l,
                     __half* __restrict__ yh,          // null on final
                     float* __restrict__ yf32,         // null unless final
                     int n)
{
    extern __shared__ __align__(1024) char smem[];
    const uint32_t sb = smem_u32(smem);
    const int tid    = threadIdx.x;
    const int lane   = tid & 31;
    const int wid    = tid >> 5;
    const int warp_m = wid >> 2;        // 0..1 -> 64 rows
    const int warp_n = wid & 3;         // 0..3 -> 32 cols
    const int m0     = blockIdx.x * 128;

    float acc[4][4][4];
    #pragma unroll
    for (int i = 0; i < 4; i++)
        #pragma unroll
        for (int j = 0; j < 4; j++)
            #pragma unroll
            for (int q = 0; q < 4; q++) acc[i][j][q] = 0.f;

    auto load_stage = [&](int stage, int c) {
        const __half* A;
        int lda;
        if (c < 2) { A = x + c * KC; lda = D_DIM; }
        else       { A = h + (c - 2) * KC; lda = R_REL * D_DIM; }
        const uint32_t base = sb + stage * ST_SIZE;
        // A: 128 rows x 64 fp16 = 1024 16B-granules
        #pragma unroll
        for (int it = 0; it < 4; it++) {
            int f   = it * 256 + tid;
            int row = f >> 3;
            int q   = f & 7;
            uint32_t off = SWZ128((uint32_t)(row * 128 + q * 16));
            int bytes = (m0 + row < n) ? 16 : 0;
            cp16z(base + ST_A + off, A + (size_t)(m0 + row) * lda + q * 8, bytes);
        }
        // B: 128 rows x 64 fp16
        #pragma unroll
        for (int it = 0; it < 4; it++) {
            int f   = it * 256 + tid;
            int row = f >> 3;
            int q   = f & 7;
            uint32_t off = SWZ128((uint32_t)(row * 128 + q * 16));
            cp16(base + ST_B + off, Wt + (size_t)row * KTOT + c * KC + q * 8);
        }
    };

    load_stage(0, 0);
    CP_COMMIT();

    for (int c = 0; c < NCHUNK; c++) {
        if (c + 1 < NCHUNK) {
            load_stage((c + 1) & 1, c + 1);
            CP_COMMIT();
            CP_WAIT(1);
        } else {
            CP_WAIT(0);
        }
        __syncthreads();

        const uint32_t base = sb + (c & 1) * ST_SIZE;
        #pragma unroll
        for (int ks = 0; ks < 4; ks++) {
            const int k0 = ks * 16;
            uint32_t b[2][4];
            #pragma unroll
            for (int p = 0; p < 2; p++) {
                int nb   = warp_n * 32 + p * 16;
                int row  = nb + (lane & 7) + ((lane >> 4) << 3);
                uint32_t off = SWZ128((uint32_t)(row * 128 + k0 * 2 + ((lane & 8) ? 16 : 0)));
                ldmatrix_x4(b[p][0], b[p][1], b[p][2], b[p][3], base + ST_B + off);
            }
            #pragma unroll
            for (int m = 0; m < 4; m++) {
                int row  = warp_m * 64 + m * 16 + (lane & 15);
                uint32_t off = SWZ128((uint32_t)(row * 128 + k0 * 2 + ((lane >> 4) << 4)));
                uint32_t a[4];
                ldmatrix_x4(a[0], a[1], a[2], a[3], base + ST_A + off);
                #pragma unroll
                for (int p = 0; p < 2; p++) {
                    #pragma unroll
                    for (int t = 0; t < 2; t++) {
                        int nt = p * 2 + t;
                        mma_f16(acc[m][nt], a, b[p][t * 2], b[p][t * 2 + 1]);
                    }
                }
            }
        }
        __syncthreads();
    }

    // ---- epilogue: bias + leaky_relu ----
    #pragma unroll
    for (int nt = 0; nt < 4; nt++) {
        int col = warp_n * 32 + nt * 8 + (lane & 3) * 2;
        float2 b = *reinterpret_cast<const float2*>(bias_l + col);
        #pragma unroll
        for (int m = 0; m < 4; m++) {
            int row0 = m0 + warp_m * 64 + m * 16 + (lane >> 2);
            #pragma unroll
            for (int half = 0; half < 2; half++) {
                int row = row0 + half * 8;
                if (row < n) {
                    float v0 = acc[m][nt][half * 2 + 0] + b.x;
                    float v1 = acc[m][nt][half * 2 + 1] + b.y;
                    v0 = v0 > 0.f ? v0 : 0.01f * v0;
                    v1 = v1 > 0.f ? v1 : 0.01f * v1;
                    if (yf32) {
                        *reinterpret_cast<float2*>(yf32 + (size_t)row * D_DIM + col) =
                            make_float2(v0, v1);
                    } else {
                        *reinterpret_cast<uint32_t*>(yh + (size_t)row * D_DIM + col) =
                            pack2h(v0, v1);
                    }
                }
            }
        }
    }
}

// ---------------------------------------------------------------------------
// Launch
// ---------------------------------------------------------------------------
extern "C" void kernel_launch(void* const* d_in, const int* in_sizes, int n_in,
                              void* d_out, int out_size)
{
    const int*   node_type  = (const int*)  d_in[0];
    const int*   edge_index = (const int*)  d_in[1];
    const int*   edge_type  = (const int*)  d_in[2];
    const float* emb        = (const float*)d_in[3];
    const float* W          = (const float*)d_in[4];   // [L,R,D,D]
    const float* root       = (const float*)d_in[5];   // [L,D,D]
    const float* bias       = (const float*)d_in[6];   // [L,D]
    float*       out        = (float*)d_out;

    const int n  = in_sizes[0];
    const int E  = in_sizes[2];
    const int n4 = n * R_REL;

    __half *xA, *xB, *h, *wt;
    int* cursor;
    cudaGetSymbolAddress((void**)&xA,  g_xA);
    cudaGetSymbolAddress((void**)&xB,  g_xB);
    cudaGetSymbolAddress((void**)&h,   g_h);
    cudaGetSymbolAddress((void**)&wt,  g_Wt);
    cudaGetSymbolAddress((void**)&cursor, g_cursor);

    cudaFuncSetAttribute(gemm_mma_kernel,
                         cudaFuncAttributeMaxDynamicSharedMemorySize, SM_TOTAL);

    // --- one-time per launch: embed+prep, edge sort ---
    cudaMemsetAsync(cursor, 0, (size_t)n4 * sizeof(int));
    {
        const int TOT   = L_LAY * D_DIM * KTOT;
        const int total = n * 32 + TOT;
        embedprep_kernel<<<(total + 255) / 256, 256>>>(node_type, emb, xA, W, root, n);
    }
    hist_kernel<<<(E + 255) / 256, 256>>>(edge_index, edge_type, E);
    {
        const int nb = (n4 + 1023) / 1024;
        scanA_kernel<<<nb, 1024>>>(n4);
        scanB_kernel<<<1, 256>>>(nb);
        scanC_kernel<<<(n4 + 1 + 1023) / 1024, 1024>>>(n4, E);
    }
    reorder_kernel<<<(E + 255) / 256, 256>>>(edge_index, edge_type, E);

    const int agg_blocks  = (n * 32 + 255) / 256;
    const int gemm_blocks = (n + 127) / 128;

    for (int l = 0; l < L_LAY; l++) {
        const __half* xin = (l == 1) ? xB : xA;
        __half*       xout = (l == 0) ? xB : xA;

        agg_kernel<<<agg_blocks, 256>>>(xin, h, n);

        if (l < L_LAY - 1) {
            gemm_mma_kernel<<<gemm_blocks, 256, SM_TOTAL>>>(
                xin, h,
                wt + (size_t)l * D_DIM * KTOT,
                bias + (size_t)l * D_DIM,
                xout, (float*)nullptr, n);
        } else {
            gemm_mma_kernel<<<gemm_blocks, 256, SM_TOTAL>>>(
                xin, h,
                wt + (size_t)l * D_DIM * KTOT,
                bias + (size_t)l * D_DIM,
                (__half*)nullptr, out, n);
        }
    }
}